// round 1
// baseline (speedup 1.0000x reference)
#include <cuda_runtime.h>
#include <math.h>

// ---------------- problem constants ----------------
#define Cc    256
#define HWp   16384      // 128*128
#define Hh    128
#define Ww    128
#define H1c   128
#define H2c   64
#define W2c   400
#define NPTS  (H1c*W2c)  // 51200
#define MQ    NPTS
#define MK    (H2c*W2c)  // 25600
#define DHc   32

// ---------------- scratch (device globals; no runtime alloc) ----------------
__device__ float  d_at[HWp*Cc];      // working image, HWC layout
__device__ float  d_aseq[MQ*Cc];     // bilinear-sampled query sequence (+pos_a)
__device__ float  d_qq[MQ*Cc];
__device__ float  d_kk[MK*Cc];
__device__ float  d_vv[MK*Cc];
__device__ float  d_o[MQ*Cc];
__device__ float  d_oproj[MQ*Cc];
__device__ float  d_rest[HWp*Cc];
__device__ float  d_enh[HWp*Cc];
__device__ float  d_cnt[HWp];
__device__ int4   d_gidx[NPTS];
__device__ float2 d_wxy[NPTS];
__device__ int    d_sidx[NPTS];
__device__ float  d_Wc[3*Cc*Cc];     // combined weights for qq/kk/vv
__device__ float  d_bc[3*Cc];        // combined biases
__device__ float  d_poskk[H2c*Cc];   // pos_b projected through combined K weights (+bias)
__device__ float  d_posvv[H2c*Cc];

// ---------------- input transpose: (C,H,W) -> (HW, C) ----------------
__global__ void k_transpose_in(const float* __restrict__ a) {
    __shared__ float tile[32][33];
    int hw0 = blockIdx.x * 32;
    int c0  = blockIdx.y * 32;
    for (int i = threadIdx.y; i < 32; i += 8)
        tile[i][threadIdx.x] = a[(size_t)(c0 + i) * HWp + hw0 + threadIdx.x];
    __syncthreads();
    for (int i = threadIdx.y; i < 32; i += 8)
        d_at[(size_t)(hw0 + i) * Cc + c0 + threadIdx.x] = tile[threadIdx.x][i];
}

// ---------------- combined weights: Wc[sel][n][c] = sum_m in_w[sel*256+n][m] * W{q,k,v}[m][c]
__global__ void k_combine_w(const float* __restrict__ Wq, const float* __restrict__ Wk,
                            const float* __restrict__ Wv, const float* __restrict__ in_w) {
    int n = blockIdx.x, sel = blockIdx.y, c = threadIdx.x;
    const float* W = (sel == 0) ? Wq : ((sel == 1) ? Wk : Wv);
    __shared__ float ir[Cc];
    ir[c] = in_w[(size_t)(sel * Cc + n) * Cc + c];
    __syncthreads();
    float s = 0.f;
    #pragma unroll 8
    for (int m = 0; m < Cc; m++) s += ir[m] * W[(size_t)m * Cc + c];
    d_Wc[(size_t)sel * Cc * Cc + (size_t)n * Cc + c] = s;
}

__global__ void k_combine_b(const float* __restrict__ bq, const float* __restrict__ bk,
                            const float* __restrict__ bv, const float* __restrict__ in_w,
                            const float* __restrict__ in_b) {
    int sel = blockIdx.x, n = threadIdx.x;
    const float* b = (sel == 0) ? bq : ((sel == 1) ? bk : bv);
    float s = in_b[sel * Cc + n];
    const float* row = in_w + (size_t)(sel * Cc + n) * Cc;
    for (int m = 0; m < Cc; m++) s += row[m] * b[m];
    d_bc[sel * Cc + n] = s;
}

// poskk[h][n] = sum_c pos_b[h][c]*Wck[n][c] + bck[n]   (and same for V)
__global__ void k_pos_proj(const float* __restrict__ pos_b) {
    int h = blockIdx.x, which = blockIdx.y, n = threadIdx.x;
    __shared__ float pb[Cc];
    pb[n] = pos_b[(size_t)h * Cc + n];
    __syncthreads();
    int sel = which + 1;  // 1 = K, 2 = V
    const float* Wrow = d_Wc + (size_t)sel * Cc * Cc + (size_t)n * Cc;
    float s = d_bc[sel * Cc + n];
    #pragma unroll 8
    for (int c = 0; c < Cc; c++) s += pb[c] * Wrow[c];
    (which == 0 ? d_poskk : d_posvv)[(size_t)h * Cc + n] = s;
}

// ---------------- per-pass coordinate/bilinear/scatter-index precompute ----------------
__global__ void k_coords(const float* __restrict__ rots, const float* __restrict__ fxs,
                         const float* __restrict__ cxs, int j) {
    int p = blockIdx.x * blockDim.x + threadIdx.x;
    if (p >= NPTS) return;
    int r = p / W2c, w = p % W2c;
    float fx = fxs[j], cx = cxs[j];
    float cth = rots[j * 9 + 0];   // cos(theta) = rots[0][0]
    float sth = rots[j * 9 + 3];   // sin(theta) = rots[1][0]
    float ang = atanf((w * 2.0f + 1.0f - cx) / fx);
    float cA = cosf(ang), sA = sinf(ang);
    float ca = sth * cA - cth * sA;
    float sa = cth * cA + sth * sA;
    float rmax = sqrtf(64.f * 64.f + 64.f * 64.f);
    float rad = ((float)r / 127.0f) * rmax;
    float x = 64.f + rad * ca;
    float y = 64.f - rad * sa;
    // bilinear prep (clip first)
    float xc = fminf(fmaxf(x, 0.f), 127.f);
    float yc = fminf(fmaxf(y, 0.f), 127.f);
    float x0 = floorf(xc), y0 = floorf(yc);
    float x1 = fminf(x0 + 1.f, 127.f), y1 = fminf(y0 + 1.f, 127.f);
    int x0i = (int)x0, x1i = (int)x1, y0i = (int)y0, y1i = (int)y1;
    d_gidx[p] = make_int4(y0i * Ww + x0i, y0i * Ww + x1i, y1i * Ww + x0i, y1i * Ww + x1i);
    d_wxy[p]  = make_float2(xc - x0, yc - y0);
    // scatter index: round (half-even) THEN clip
    int xi = (int)fminf(fmaxf(rintf(x), 0.f), 127.f);
    int yi = (int)fminf(fmaxf(rintf(y), 0.f), 127.f);
    d_sidx[p] = yi * Ww + xi;
}

// ---------------- a_seq = bilinear(a_t) + pos_a,  row = w*128 + r ----------------
__global__ void k_build_aseq(const float* __restrict__ pos_a) {
    int p = blockIdx.x, c = threadIdx.x;
    int r = p / W2c, w = p % W2c;
    int4 g = d_gidx[p];
    float2 wt = d_wxy[p];
    float v00 = d_at[(size_t)g.x * Cc + c];
    float v01 = d_at[(size_t)g.y * Cc + c];
    float v10 = d_at[(size_t)g.z * Cc + c];
    float v11 = d_at[(size_t)g.w * Cc + c];
    float wx = wt.x, wy = wt.y;
    float val = v00 * (1.f - wx) * (1.f - wy) + v01 * wx * (1.f - wy)
              + v10 * (1.f - wx) * wy + v11 * wx * wy;
    int row = w * H1c + r;
    d_aseq[(size_t)row * Cc + c] = val + pos_a[(size_t)r * Cc + c];
}

// ---------------- SGEMM: C[M,256] = A . B^T + bias ----------------
// AMODE 0: A row-major [M][256].  AMODE 1: A K-major [256][lda] (element A[k*lda+m]).
// B is [256][256] row-major (weight [n][k]).
// BIASMODE 0: bias[n].  BIASMODE 1: bias[(m/400)*256 + n].
template<int AMODE, int BIASMODE>
__global__ __launch_bounds__(256) void k_sgemm(const float* __restrict__ A,
                                               const float* __restrict__ B,
                                               const float* __restrict__ bias,
                                               float* __restrict__ Cmat, int lda) {
    __shared__ __align__(16) float As[8][128];
    __shared__ __align__(16) float Bs[8][128];
    int t  = threadIdx.x;
    int m0 = blockIdx.x * 128;
    int n0 = blockIdx.y * 128;
    int tm = (t / 16) * 8;
    int tn = (t % 16) * 8;
    float acc[8][8] = {};
    for (int k0 = 0; k0 < 256; k0 += 8) {
        if (AMODE == 0) {
            int row = t >> 1;
            int kq  = (t & 1) * 4;
            float4 v = *reinterpret_cast<const float4*>(A + (size_t)(m0 + row) * 256 + k0 + kq);
            As[kq + 0][row] = v.x; As[kq + 1][row] = v.y;
            As[kq + 2][row] = v.z; As[kq + 3][row] = v.w;
        } else {
            int k = t >> 5;
            int m = (t & 31) * 4;
            float4 v = *reinterpret_cast<const float4*>(A + (size_t)(k0 + k) * lda + m0 + m);
            *reinterpret_cast<float4*>(&As[k][m]) = v;
        }
        {
            int row = t >> 1;
            int kq  = (t & 1) * 4;
            float4 v = *reinterpret_cast<const float4*>(B + (size_t)(n0 + row) * 256 + k0 + kq);
            Bs[kq + 0][row] = v.x; Bs[kq + 1][row] = v.y;
            Bs[kq + 2][row] = v.z; Bs[kq + 3][row] = v.w;
        }
        __syncthreads();
        #pragma unroll
        for (int kk = 0; kk < 8; kk++) {
            float4 ra0 = *reinterpret_cast<const float4*>(&As[kk][tm]);
            float4 ra1 = *reinterpret_cast<const float4*>(&As[kk][tm + 4]);
            float4 rb0 = *reinterpret_cast<const float4*>(&Bs[kk][tn]);
            float4 rb1 = *reinterpret_cast<const float4*>(&Bs[kk][tn + 4]);
            float ra[8] = {ra0.x, ra0.y, ra0.z, ra0.w, ra1.x, ra1.y, ra1.z, ra1.w};
            float rb[8] = {rb0.x, rb0.y, rb0.z, rb0.w, rb1.x, rb1.y, rb1.z, rb1.w};
            #pragma unroll
            for (int i = 0; i < 8; i++)
                #pragma unroll
                for (int jj = 0; jj < 8; jj++)
                    acc[i][jj] += ra[i] * rb[jj];
        }
        __syncthreads();
    }
    #pragma unroll
    for (int i = 0; i < 8; i++) {
        int m = m0 + tm + i;
        #pragma unroll
        for (int jj = 0; jj < 8; jj++) {
            int n = n0 + tn + jj;
            float b = (BIASMODE == 0) ? bias[n] : bias[(size_t)(m / 400) * 256 + n];
            Cmat[(size_t)m * 256 + n] = acc[i][jj] + b;
        }
    }
}

// ---------------- attention: grid (w=400, head=8), 128 threads (one per q-row r) ----------------
__global__ __launch_bounds__(128) void k_attn() {
    int w = blockIdx.x, h = blockIdx.y, r = threadIdx.x;
    __shared__ float Ks[H2c * DHc];
    __shared__ float Vs[H2c * DHc];
    for (int i = r; i < H2c * DHc; i += 128) {
        int hh = i >> 5, d = i & 31;
        size_t src = (size_t)(hh * W2c + w) * Cc + h * DHc + d;
        Ks[i] = d_kk[src];
        Vs[i] = d_vv[src];
    }
    __syncthreads();
    float q[DHc];
    const float* qp = d_qq + (size_t)(w * H1c + r) * Cc + h * DHc;
    #pragma unroll
    for (int d = 0; d < DHc; d++) q[d] = qp[d];
    float s[H2c];
    float mx = -INFINITY;
    #pragma unroll
    for (int k = 0; k < H2c; k++) {
        float a = 0.f;
        #pragma unroll
        for (int d = 0; d < DHc; d++) a += q[d] * Ks[k * DHc + d];
        a *= 0.17677669529663687f;  // 1/sqrt(32)
        s[k] = a;
        mx = fmaxf(mx, a);
    }
    float sum = 0.f;
    #pragma unroll
    for (int k = 0; k < H2c; k++) { s[k] = expf(s[k] - mx); sum += s[k]; }
    float inv = 1.f / sum;
    float acc[DHc] = {};
    #pragma unroll
    for (int k = 0; k < H2c; k++) {
        float p = s[k] * inv;
        #pragma unroll
        for (int d = 0; d < DHc; d++) acc[d] += p * Vs[k * DHc + d];
    }
    float* op = d_o + (size_t)(w * H1c + r) * Cc + h * DHc;
    #pragma unroll
    for (int d = 0; d < DHc; d++) op[d] = acc[d];
}

// ---------------- scatter-add into rest / cnt ----------------
__global__ void k_zero() {
    size_t i = (size_t)blockIdx.x * 256 + threadIdx.x;
    if (i < (size_t)HWp * Cc) d_rest[i] = 0.f;
    if (i < HWp) d_cnt[i] = 0.f;
}

__global__ void k_scatter() {
    int p = blockIdx.x, c = threadIdx.x;
    int r = p / W2c, w = p % W2c;
    int row = w * H1c + r;
    int si = d_sidx[p];
    atomicAdd(&d_rest[(size_t)si * Cc + c], d_oproj[(size_t)row * Cc + c]);
    if (c == 0) atomicAdd(&d_cnt[si], 1.0f);
}

__global__ void k_update() {
    int hw = blockIdx.x, c = threadIdx.x;
    float cnt = d_cnt[hw];
    cnt = (cnt == 0.f) ? 1.f : cnt;
    float e = d_rest[(size_t)hw * Cc + c] / cnt;
    d_enh[(size_t)hw * Cc + c] = e;
    d_at[(size_t)hw * Cc + c] += e;
}

// ---------------- final: out[c][hw] = a_t[hw][c] + enh[hw][c] ----------------
__global__ void k_writeout(float* __restrict__ out) {
    __shared__ float tile[32][33];
    int hw0 = blockIdx.x * 32;
    int c0  = blockIdx.y * 32;
    for (int i = threadIdx.y; i < 32; i += 8) {
        size_t idx = (size_t)(hw0 + i) * Cc + c0 + threadIdx.x;
        tile[i][threadIdx.x] = d_at[idx] + d_enh[idx];
    }
    __syncthreads();
    for (int i = threadIdx.y; i < 32; i += 8)
        out[(size_t)(c0 + i) * HWp + hw0 + threadIdx.x] = tile[threadIdx.x][i];
}

// ---------------- host launcher ----------------
extern "C" void kernel_launch(void* const* d_in, const int* in_sizes, int n_in,
                              void* d_out, int out_size) {
    const float* list_a = (const float*)d_in[0];
    const float* list_b = (const float*)d_in[1];
    const float* rots   = (const float*)d_in[3];
    const float* fxs    = (const float*)d_in[5];
    const float* cxs    = (const float*)d_in[6];
    const float* pos_a  = (const float*)d_in[7];
    const float* pos_b  = (const float*)d_in[8];
    const float* Wq     = (const float*)d_in[9];
    const float* bq     = (const float*)d_in[10];
    const float* Wk     = (const float*)d_in[11];
    const float* bk     = (const float*)d_in[12];
    const float* Wv     = (const float*)d_in[13];
    const float* bv     = (const float*)d_in[14];
    const float* in_w   = (const float*)d_in[15];
    const float* in_b   = (const float*)d_in[16];
    const float* out_w  = (const float*)d_in[17];
    const float* out_b  = (const float*)d_in[18];
    float* out = (float*)d_out;

    // resolve scratch symbol addresses (host-side query; graph-capture safe)
    float *p_aseq, *p_qq, *p_kk, *p_vv, *p_o, *p_oproj, *p_Wc, *p_bc, *p_poskk, *p_posvv;
    cudaGetSymbolAddress((void**)&p_aseq,  d_aseq);
    cudaGetSymbolAddress((void**)&p_qq,    d_qq);
    cudaGetSymbolAddress((void**)&p_kk,    d_kk);
    cudaGetSymbolAddress((void**)&p_vv,    d_vv);
    cudaGetSymbolAddress((void**)&p_o,     d_o);
    cudaGetSymbolAddress((void**)&p_oproj, d_oproj);
    cudaGetSymbolAddress((void**)&p_Wc,    d_Wc);
    cudaGetSymbolAddress((void**)&p_bc,    d_bc);
    cudaGetSymbolAddress((void**)&p_poskk, d_poskk);
    cudaGetSymbolAddress((void**)&p_posvv, d_posvv);

    // init: working image + combined weights
    k_transpose_in<<<dim3(HWp / 32, Cc / 32), dim3(32, 8)>>>(list_a);
    k_combine_w<<<dim3(Cc, 3), Cc>>>(Wq, Wk, Wv, in_w);
    k_combine_b<<<3, Cc>>>(bq, bk, bv, in_w, in_b);
    k_pos_proj<<<dim3(H2c, 2), Cc>>>(pos_b);

    const int cams[2] = {0, 3};
    for (int ji = 0; ji < 2; ji++) {
        int j = cams[ji];
        k_zero<<<HWp, 256>>>();
        k_coords<<<(NPTS + 255) / 256, 256>>>(rots, fxs, cxs, j);
        k_build_aseq<<<NPTS, Cc>>>(pos_a);
        // qq = a_seq @ Wcq^T + bcq
        k_sgemm<0, 0><<<dim3(MQ / 128, 2), 256>>>(p_aseq, p_Wc, p_bc, p_qq, 256);
        // kk/vv directly from list_b (K-major A), pos_b folded into per-h bias
        const float* bbase = list_b + (size_t)j * Cc * MK;
        k_sgemm<1, 1><<<dim3(MK / 128, 2), 256>>>(bbase, p_Wc + Cc * Cc,     p_poskk, p_kk, MK);
        k_sgemm<1, 1><<<dim3(MK / 128, 2), 256>>>(bbase, p_Wc + 2 * Cc * Cc, p_posvv, p_vv, MK);
        // attention
        k_attn<<<dim3(W2c, 8), 128>>>();
        // output projection
        k_sgemm<0, 0><<<dim3(MQ / 128, 2), 256>>>(p_o, out_w, out_b, p_oproj, 256);
        // scatter-mean + residual update
        k_scatter<<<NPTS, Cc>>>();
        k_update<<<HWp, Cc>>>();
    }
    k_writeout<<<dim3(HWp / 32, Cc / 32), dim3(32, 8)>>>(out);
}

// round 2
// speedup vs baseline: 2.0370x; 2.0370x over previous
#include <cuda_runtime.h>
#include <cuda_bf16.h>
#include <math.h>

// ---------------- problem constants ----------------
#define Cc    256
#define HWp   16384      // 128*128
#define Ww    128
#define H1c   128
#define H2c   64
#define W2c   400
#define NPTS  (H1c*W2c)  // 51200
#define MQ    NPTS
#define MK    (H2c*W2c)  // 25600
#define DHc   32

// ---------------- scratch (device globals; no runtime alloc) ----------------
__device__ float  d_at[HWp*Cc];            // working image, HWC layout
__device__ __nv_bfloat16 d_aseqbf[MQ*Cc];  // bilinear-sampled query sequence (+pos_a), bf16
__device__ __nv_bfloat16 d_btbf[MK*Cc];    // list_b slice transposed to [M][K] bf16
__device__ float  d_qq[MQ*Cc];
__device__ float  d_kk[MK*Cc];
__device__ float  d_vv[MK*Cc];
__device__ __nv_bfloat16 d_obf[MQ*Cc];     // attention output, bf16
__device__ float  d_oproj[MQ*Cc];
__device__ float  d_rest[HWp*Cc];
__device__ float  d_enh[HWp*Cc];
__device__ float  d_cnt[HWp];
__device__ int4   d_gidx[NPTS];
__device__ float2 d_wxy[NPTS];
__device__ int    d_sidx[NPTS];
__device__ float  d_Wc[3*Cc*Cc];           // combined q/k/v weights fp32 [sel][n][k]
__device__ float  d_bc[3*Cc];              // combined biases
__device__ __nv_bfloat16 d_WcT[3*Cc*Cc];   // combined weights bf16, K-major [sel][k][n]
__device__ __nv_bfloat16 d_outwT[Cc*Cc];   // out_w bf16 K-major [k][n]
__device__ float  d_poskk[H2c*Cc];         // pos_b projected through combined K weights (+bias)
__device__ float  d_posvv[H2c*Cc];

__device__ __forceinline__ unsigned sptr(const void* p) {
    return (unsigned)__cvta_generic_to_shared(p);
}

#define LDMX4(r0,r1,r2,r3,addr) \
    asm volatile("ldmatrix.sync.aligned.m8n8.x4.shared.b16 {%0,%1,%2,%3},[%4];" \
        : "=r"(r0),"=r"(r1),"=r"(r2),"=r"(r3) : "r"(addr))
#define LDMX4T(r0,r1,r2,r3,addr) \
    asm volatile("ldmatrix.sync.aligned.m8n8.x4.trans.shared.b16 {%0,%1,%2,%3},[%4];" \
        : "=r"(r0),"=r"(r1),"=r"(r2),"=r"(r3) : "r"(addr))
#define MMABF16(c0,c1,c2,c3,a0,a1,a2,a3,b0,b1) \
    asm volatile("mma.sync.aligned.m16n8k16.row.col.f32.bf16.bf16.f32 " \
        "{%0,%1,%2,%3},{%4,%5,%6,%7},{%8,%9},{%0,%1,%2,%3};" \
        : "+f"(c0),"+f"(c1),"+f"(c2),"+f"(c3) \
        : "r"(a0),"r"(a1),"r"(a2),"r"(a3),"r"(b0),"r"(b1))

// ---------------- input transpose: (C,H,W) -> (HW, C) ----------------
__global__ void k_transpose_in(const float* __restrict__ a) {
    __shared__ float tile[32][33];
    int hw0 = blockIdx.x * 32;
    int c0  = blockIdx.y * 32;
    for (int i = threadIdx.y; i < 32; i += 8)
        tile[i][threadIdx.x] = a[(size_t)(c0 + i) * HWp + hw0 + threadIdx.x];
    __syncthreads();
    for (int i = threadIdx.y; i < 32; i += 8)
        d_at[(size_t)(hw0 + i) * Cc + c0 + threadIdx.x] = tile[threadIdx.x][i];
}

// ---------------- combined weights: Wc[sel][n][c] = sum_m in_w[sel*256+n][m] * W{q,k,v}[m][c]
__global__ void k_combine_w(const float* __restrict__ Wq, const float* __restrict__ Wk,
                            const float* __restrict__ Wv, const float* __restrict__ in_w) {
    int n = blockIdx.x, sel = blockIdx.y, c = threadIdx.x;
    const float* W = (sel == 0) ? Wq : ((sel == 1) ? Wk : Wv);
    __shared__ float ir[Cc];
    ir[c] = in_w[(size_t)(sel * Cc + n) * Cc + c];
    __syncthreads();
    float s = 0.f;
    #pragma unroll 8
    for (int m = 0; m < Cc; m++) s += ir[m] * W[(size_t)m * Cc + c];
    d_Wc[(size_t)sel * Cc * Cc + (size_t)n * Cc + c] = s;
}

__global__ void k_combine_b(const float* __restrict__ bq, const float* __restrict__ bk,
                            const float* __restrict__ bv, const float* __restrict__ in_w,
                            const float* __restrict__ in_b) {
    int sel = blockIdx.x, n = threadIdx.x;
    const float* b = (sel == 0) ? bq : ((sel == 1) ? bk : bv);
    float s = in_b[sel * Cc + n];
    const float* row = in_w + (size_t)(sel * Cc + n) * Cc;
    for (int m = 0; m < Cc; m++) s += row[m] * b[m];
    d_bc[sel * Cc + n] = s;
}

// ---------------- transpose+convert weight [n][k] fp32 -> [k][n] bf16 ----------------
__global__ void k_w2bt(const float* __restrict__ src, __nv_bfloat16* __restrict__ dst) {
    __shared__ float tile[32][33];
    int n0 = blockIdx.x * 32, k0 = blockIdx.y * 32;
    int tx = threadIdx.x;
    for (int i = threadIdx.y; i < 32; i += 8)
        tile[i][tx] = src[(size_t)(n0 + i) * Cc + k0 + tx];
    __syncthreads();
    for (int i = threadIdx.y; i < 32; i += 8)
        dst[(size_t)(k0 + i) * Cc + n0 + tx] = __float2bfloat16_rn(tile[tx][i]);
}

// ---------------- transpose+convert list_b slice [C][M] fp32 -> [M][C] bf16 --------
__global__ void k_b2bt(const float* __restrict__ src) {
    __shared__ float tile[32][33];
    int m0 = blockIdx.x * 32, c0 = blockIdx.y * 32;
    int tx = threadIdx.x;
    for (int i = threadIdx.y; i < 32; i += 8)
        tile[i][tx] = src[(size_t)(c0 + i) * MK + m0 + tx];
    __syncthreads();
    for (int i = threadIdx.y; i < 32; i += 8)
        d_btbf[(size_t)(m0 + i) * Cc + c0 + tx] = __float2bfloat16_rn(tile[tx][i]);
}

// poskk[h][n] = sum_c pos_b[h][c]*WcT_k[c][n] + bck[n]   (and same for V) — coalesced
__global__ void k_pos_proj(const float* __restrict__ pos_b) {
    int h = blockIdx.x, which = blockIdx.y, n = threadIdx.x;
    __shared__ float pb[Cc];
    pb[n] = pos_b[(size_t)h * Cc + n];
    __syncthreads();
    int sel = which + 1;  // 1 = K, 2 = V
    const __nv_bfloat16* W = d_WcT + (size_t)sel * Cc * Cc;
    float s = d_bc[sel * Cc + n];
    #pragma unroll 8
    for (int c = 0; c < Cc; c++) s += pb[c] * __bfloat162float(W[(size_t)c * Cc + n]);
    (which == 0 ? d_poskk : d_posvv)[(size_t)h * Cc + n] = s;
}

// ---------------- per-pass coordinate/bilinear/scatter-index precompute ----------------
__global__ void k_coords(const float* __restrict__ rots, const float* __restrict__ fxs,
                         const float* __restrict__ cxs, int j) {
    int p = blockIdx.x * blockDim.x + threadIdx.x;
    if (p >= NPTS) return;
    int r = p / W2c, w = p % W2c;
    float fx = fxs[j], cx = cxs[j];
    float cth = rots[j * 9 + 0];
    float sth = rots[j * 9 + 3];
    float ang = atanf((w * 2.0f + 1.0f - cx) / fx);
    float cA = cosf(ang), sA = sinf(ang);
    float ca = sth * cA - cth * sA;
    float sa = cth * cA + sth * sA;
    float rmax = sqrtf(64.f * 64.f + 64.f * 64.f);
    float rad = ((float)r / 127.0f) * rmax;
    float x = 64.f + rad * ca;
    float y = 64.f - rad * sa;
    float xc = fminf(fmaxf(x, 0.f), 127.f);
    float yc = fminf(fmaxf(y, 0.f), 127.f);
    float x0 = floorf(xc), y0 = floorf(yc);
    float x1 = fminf(x0 + 1.f, 127.f), y1 = fminf(y0 + 1.f, 127.f);
    int x0i = (int)x0, x1i = (int)x1, y0i = (int)y0, y1i = (int)y1;
    d_gidx[p] = make_int4(y0i * Ww + x0i, y0i * Ww + x1i, y1i * Ww + x0i, y1i * Ww + x1i);
    d_wxy[p]  = make_float2(xc - x0, yc - y0);
    int xi = (int)fminf(fmaxf(rintf(x), 0.f), 127.f);
    int yi = (int)fminf(fmaxf(rintf(y), 0.f), 127.f);
    d_sidx[p] = yi * Ww + xi;
}

// ---------------- a_seq = bilinear(a_t) + pos_a  ->  bf16, row = w*128 + r ----------------
__global__ void k_build_aseq(const float* __restrict__ pos_a) {
    int p = blockIdx.x, c = threadIdx.x;
    int r = p / W2c, w = p % W2c;
    int4 g = d_gidx[p];
    float2 wt = d_wxy[p];
    float v00 = d_at[(size_t)g.x * Cc + c];
    float v01 = d_at[(size_t)g.y * Cc + c];
    float v10 = d_at[(size_t)g.z * Cc + c];
    float v11 = d_at[(size_t)g.w * Cc + c];
    float wx = wt.x, wy = wt.y;
    float val = v00 * (1.f - wx) * (1.f - wy) + v01 * wx * (1.f - wy)
              + v10 * (1.f - wx) * wy + v11 * wx * wy;
    int row = w * H1c + r;
    d_aseqbf[(size_t)row * Cc + c] = __float2bfloat16_rn(val + pos_a[(size_t)r * Cc + c]);
}

// ---------------- tensor-core GEMM: C[M,256] = A[M,256] . BT^T + bias  (bf16 mma) ----
// A bf16 row-major [M][256]; BT bf16 K-major [256][256] (BT[k][n] = W[n][k]).
// BIASMODE 0: bias[n].  BIASMODE 1: bias[(m/400)*256 + n].
template<int BIASMODE>
__global__ __launch_bounds__(256) void k_mma_gemm(const __nv_bfloat16* __restrict__ A,
                                                  const __nv_bfloat16* __restrict__ BT,
                                                  const float* __restrict__ bias,
                                                  float* __restrict__ C) {
    __shared__ __align__(16) __nv_bfloat16 As[2][128][40];   // K tile 32, pad to 40
    __shared__ __align__(16) __nv_bfloat16 Bs[2][32][136];   // [k][n], pad 128->136
    int t = threadIdx.x;
    int m0 = blockIdx.x * 128, n0 = blockIdx.y * 128;
    int lane = t & 31, warp = t >> 5;
    int wm = (warp & 3) * 32;   // warp m-offset within tile
    int wn = (warp >> 2) * 64;  // warp n-offset within tile

    // ldg/sts slot mapping (2 slots per thread for each of A,B)
    int am = t >> 2, ak = (t & 3) * 8;
    int bk = t >> 4, bn = (t & 15) * 8;
    const __nv_bfloat16* Ag = A + (size_t)(m0 + am) * Cc + ak;
    const __nv_bfloat16* Bg = BT + (size_t)bk * Cc + n0 + bn;

    float4 va0 = *(const float4*)(Ag);
    float4 va1 = *(const float4*)(Ag + 64 * Cc);
    float4 vb0 = *(const float4*)(Bg);
    float4 vb1 = *(const float4*)(Bg + 16 * Cc);
    *(float4*)&As[0][am][ak]      = va0;
    *(float4*)&As[0][am + 64][ak] = va1;
    *(float4*)&Bs[0][bk][bn]      = vb0;
    *(float4*)&Bs[0][bk + 16][bn] = vb1;
    __syncthreads();

    float acc[2][8][4];
    #pragma unroll
    for (int i = 0; i < 2; i++)
        #pragma unroll
        for (int j = 0; j < 8; j++)
            #pragma unroll
            for (int q = 0; q < 4; q++) acc[i][j][q] = 0.f;

    #pragma unroll 1
    for (int iter = 0; iter < 8; iter++) {
        int buf = iter & 1;
        if (iter < 7) {
            int k0 = (iter + 1) * 32;
            va0 = *(const float4*)(Ag + k0);
            va1 = *(const float4*)(Ag + 64 * Cc + k0);
            vb0 = *(const float4*)(Bg + (size_t)k0 * Cc);
            vb1 = *(const float4*)(Bg + (size_t)(k0 + 16) * Cc);
        }
        #pragma unroll
        for (int kk = 0; kk < 32; kk += 16) {
            unsigned a[2][4], b[8][2];
            #pragma unroll
            for (int i = 0; i < 2; i++) {
                unsigned addr = sptr(&As[buf][wm + i * 16 + (lane & 15)][kk + (lane >> 4) * 8]);
                LDMX4(a[i][0], a[i][1], a[i][2], a[i][3], addr);
            }
            #pragma unroll
            for (int j = 0; j < 4; j++) {
                unsigned addr = sptr(&Bs[buf][kk + (lane & 15)][wn + j * 16 + (lane >> 4) * 8]);
                unsigned r0, r1, r2, r3;
                LDMX4T(r0, r1, r2, r3, addr);
                b[2 * j][0] = r0; b[2 * j][1] = r1;
                b[2 * j + 1][0] = r2; b[2 * j + 1][1] = r3;
            }
            #pragma unroll
            for (int i = 0; i < 2; i++)
                #pragma unroll
                for (int j = 0; j < 8; j++)
                    MMABF16(acc[i][j][0], acc[i][j][1], acc[i][j][2], acc[i][j][3],
                            a[i][0], a[i][1], a[i][2], a[i][3], b[j][0], b[j][1]);
        }
        if (iter < 7) {
            int nb = buf ^ 1;
            *(float4*)&As[nb][am][ak]      = va0;
            *(float4*)&As[nb][am + 64][ak] = va1;
            *(float4*)&Bs[nb][bk][bn]      = vb0;
            *(float4*)&Bs[nb][bk + 16][bn] = vb1;
        }
        __syncthreads();
    }

    // epilogue
    #pragma unroll
    for (int i = 0; i < 2; i++) {
        int mrow = m0 + wm + i * 16 + (lane >> 2);
        #pragma unroll
        for (int j = 0; j < 8; j++) {
            int n = n0 + wn + j * 8 + (lane & 3) * 2;
            float b0, b1, b2, b3;
            if (BIASMODE == 0) {
                b0 = bias[n]; b1 = bias[n + 1]; b2 = b0; b3 = b1;
            } else {
                int h0 = mrow / 400, h1 = (mrow + 8) / 400;
                b0 = bias[(size_t)h0 * Cc + n]; b1 = bias[(size_t)h0 * Cc + n + 1];
                b2 = bias[(size_t)h1 * Cc + n]; b3 = bias[(size_t)h1 * Cc + n + 1];
            }
            *(float2*)&C[(size_t)mrow * Cc + n] =
                make_float2(acc[i][j][0] + b0, acc[i][j][1] + b1);
            *(float2*)&C[(size_t)(mrow + 8) * Cc + n] =
                make_float2(acc[i][j][2] + b2, acc[i][j][3] + b3);
        }
    }
}

// ---------------- attention: grid (w=400, head=8), 128 threads (one per q-row r) ----------------
__global__ __launch_bounds__(128) void k_attn() {
    int w = blockIdx.x, h = blockIdx.y, r = threadIdx.x;
    __shared__ float Ks[H2c * DHc];
    __shared__ float Vs[H2c * DHc];
    for (int i = r; i < H2c * DHc; i += 128) {
        int hh = i >> 5, d = i & 31;
        size_t src = (size_t)(hh * W2c + w) * Cc + h * DHc + d;
        Ks[i] = d_kk[src];
        Vs[i] = d_vv[src];
    }
    __syncthreads();
    float q[DHc];
    const float* qp = d_qq + (size_t)(w * H1c + r) * Cc + h * DHc;
    #pragma unroll
    for (int d = 0; d < DHc; d++) q[d] = qp[d];
    float s[H2c];
    float mx = -INFINITY;
    #pragma unroll
    for (int k = 0; k < H2c; k++) {
        float a = 0.f;
        #pragma unroll
        for (int d = 0; d < DHc; d++) a += q[d] * Ks[k * DHc + d];
        a *= 0.17677669529663687f;  // 1/sqrt(32)
        s[k] = a;
        mx = fmaxf(mx, a);
    }
    float sum = 0.f;
    #pragma unroll
    for (int k = 0; k < H2c; k++) { s[k] = expf(s[k] - mx); sum += s[k]; }
    float inv = 1.f / sum;
    float acc[DHc] = {};
    #pragma unroll
    for (int k = 0; k < H2c; k++) {
        float p = s[k] * inv;
        #pragma unroll
        for (int d = 0; d < DHc; d++) acc[d] += p * Vs[k * DHc + d];
    }
    __nv_bfloat16* op = d_obf + (size_t)(w * H1c + r) * Cc + h * DHc;
    #pragma unroll
    for (int d = 0; d < DHc; d++) op[d] = __float2bfloat16_rn(acc[d]);
}

// ---------------- scatter-add into rest / cnt ----------------
__global__ void k_zero() {
    size_t i = (size_t)blockIdx.x * 256 + threadIdx.x;
    if (i < (size_t)HWp * Cc) d_rest[i] = 0.f;
    if (i < HWp) d_cnt[i] = 0.f;
}

__global__ void k_scatter() {
    int p = blockIdx.x, c = threadIdx.x;
    int r = p / W2c, w = p % W2c;
    int row = w * H1c + r;
    int si = d_sidx[p];
    atomicAdd(&d_rest[(size_t)si * Cc + c], d_oproj[(size_t)row * Cc + c]);
    if (c == 0) atomicAdd(&d_cnt[si], 1.0f);
}

__global__ void k_update() {
    int hw = blockIdx.x, c = threadIdx.x;
    float cnt = d_cnt[hw];
    cnt = (cnt == 0.f) ? 1.f : cnt;
    float e = d_rest[(size_t)hw * Cc + c] / cnt;
    d_enh[(size_t)hw * Cc + c] = e;
    d_at[(size_t)hw * Cc + c] += e;
}

// ---------------- final: out[c][hw] = a_t[hw][c] + enh[hw][c] ----------------
__global__ void k_writeout(float* __restrict__ out) {
    __shared__ float tile[32][33];
    int hw0 = blockIdx.x * 32;
    int c0  = blockIdx.y * 32;
    for (int i = threadIdx.y; i < 32; i += 8) {
        size_t idx = (size_t)(hw0 + i) * Cc + c0 + threadIdx.x;
        tile[i][threadIdx.x] = d_at[idx] + d_enh[idx];
    }
    __syncthreads();
    for (int i = threadIdx.y; i < 32; i += 8)
        out[(size_t)(c0 + i) * HWp + hw0 + threadIdx.x] = tile[threadIdx.x][i];
}

// ---------------- host launcher ----------------
extern "C" void kernel_launch(void* const* d_in, const int* in_sizes, int n_in,
                              void* d_out, int out_size) {
    const float* list_a = (const float*)d_in[0];
    const float* list_b = (const float*)d_in[1];
    const float* rots   = (const float*)d_in[3];
    const float* fxs    = (const float*)d_in[5];
    const float* cxs    = (const float*)d_in[6];
    const float* pos_a  = (const float*)d_in[7];
    const float* pos_b  = (const float*)d_in[8];
    const float* Wq     = (const float*)d_in[9];
    const float* bq     = (const float*)d_in[10];
    const float* Wk     = (const float*)d_in[11];
    const float* bk     = (const float*)d_in[12];
    const float* Wv     = (const float*)d_in[13];
    const float* bv     = (const float*)d_in[14];
    const float* in_w   = (const float*)d_in[15];
    const float* in_b   = (const float*)d_in[16];
    const float* out_w  = (const float*)d_in[17];
    const float* out_b  = (const float*)d_in[18];
    float* out = (float*)d_out;

    float *p_Wc, *p_bc, *p_poskk, *p_posvv, *p_qq, *p_kk, *p_vv, *p_oproj;
    __nv_bfloat16 *p_aseqbf, *p_btbf, *p_obf, *p_WcT, *p_outwT;
    cudaGetSymbolAddress((void**)&p_Wc,     d_Wc);
    cudaGetSymbolAddress((void**)&p_bc,     d_bc);
    cudaGetSymbolAddress((void**)&p_poskk,  d_poskk);
    cudaGetSymbolAddress((void**)&p_posvv,  d_posvv);
    cudaGetSymbolAddress((void**)&p_qq,     d_qq);
    cudaGetSymbolAddress((void**)&p_kk,     d_kk);
    cudaGetSymbolAddress((void**)&p_vv,     d_vv);
    cudaGetSymbolAddress((void**)&p_oproj,  d_oproj);
    cudaGetSymbolAddress((void**)&p_aseqbf, d_aseqbf);
    cudaGetSymbolAddress((void**)&p_btbf,   d_btbf);
    cudaGetSymbolAddress((void**)&p_obf,    d_obf);
    cudaGetSymbolAddress((void**)&p_WcT,    d_WcT);
    cudaGetSymbolAddress((void**)&p_outwT,  d_outwT);

    // init: working image + combined weights (fp32) + K-major bf16 copies
    k_transpose_in<<<dim3(HWp / 32, Cc / 32), dim3(32, 8)>>>(list_a);
    k_combine_w<<<dim3(Cc, 3), Cc>>>(Wq, Wk, Wv, in_w);
    k_combine_b<<<3, Cc>>>(bq, bk, bv, in_w, in_b);
    for (int s = 0; s < 3; s++)
        k_w2bt<<<dim3(8, 8), dim3(32, 8)>>>(p_Wc + (size_t)s * Cc * Cc, p_WcT + (size_t)s * Cc * Cc);
    k_w2bt<<<dim3(8, 8), dim3(32, 8)>>>(out_w, p_outwT);
    k_pos_proj<<<dim3(H2c, 2), Cc>>>(pos_b);

    const int cams[2] = {0, 3};
    for (int ji = 0; ji < 2; ji++) {
        int j = cams[ji];
        k_zero<<<HWp, 256>>>();
        k_coords<<<(NPTS + 255) / 256, 256>>>(rots, fxs, cxs, j);
        k_build_aseq<<<NPTS, Cc>>>(pos_a);
        k_b2bt<<<dim3(MK / 32, Cc / 32), dim3(32, 8)>>>(list_b + (size_t)j * Cc * MK);
        // qq = a_seq @ Wcq^T + bcq
        k_mma_gemm<0><<<dim3(MQ / 128, 2), 256>>>(p_aseqbf, p_WcT, p_bc, p_qq);
        // kk/vv from transposed list_b, pos_b folded into per-h bias
        k_mma_gemm<1><<<dim3(MK / 128, 2), 256>>>(p_btbf, p_WcT + Cc * Cc,     p_poskk, p_kk);
        k_mma_gemm<1><<<dim3(MK / 128, 2), 256>>>(p_btbf, p_WcT + 2 * Cc * Cc, p_posvv, p_vv);
        // attention
        k_attn<<<dim3(W2c, 8), 128>>>();
        // output projection
        k_mma_gemm<0><<<dim3(MQ / 128, 2), 256>>>(p_obf, p_outwT, out_b, p_oproj);
        // scatter-mean + residual update
        k_scatter<<<NPTS, Cc>>>();
        k_update<<<HWp, Cc>>>();
    }
    k_writeout<<<dim3(HWp / 32, Cc / 32), dim3(32, 8)>>>(out);
}

// round 3
// speedup vs baseline: 2.7517x; 1.3508x over previous
#include <cuda_runtime.h>
#include <cuda_bf16.h>
#include <math.h>

// ---------------- problem constants ----------------
#define Cc    256
#define HWp   16384      // 128*128
#define Ww    128
#define H1c   128
#define H2c   64
#define W2c   400
#define NPTS  (H1c*W2c)  // 51200
#define MQ    NPTS
#define MK    (H2c*W2c)  // 25600
#define DHc   32

// ---------------- scratch (device globals; no runtime alloc) ----------------
__device__ float  d_at[HWp*Cc];            // working image, HWC layout
__device__ __nv_bfloat16 d_aseqbf[MQ*Cc];  // bilinear-sampled query sequence (+pos_a), bf16
__device__ __nv_bfloat16 d_btbf[MK*Cc];    // list_b slice transposed to [M][K] bf16
__device__ float  d_qq[MQ*Cc];
__device__ float  d_kk[MK*Cc];
__device__ float  d_vv[MK*Cc];
__device__ __nv_bfloat16 d_obf[MQ*Cc];     // attention output, bf16
__device__ float  d_oproj[MQ*Cc];
__device__ float  d_rest[HWp*Cc];
__device__ float  d_enh[HWp*Cc];
__device__ float  d_cnt[HWp];
__device__ int4   d_gidx[2*NPTS];          // both passes precomputed
__device__ float2 d_wxy[2*NPTS];
__device__ int    d_sidx[2*NPTS];
__device__ float  d_Wc[3*Cc*Cc];           // combined q/k/v weights fp32 [sel][n][k]
__device__ float  d_bc[3*Cc];              // combined biases
__device__ __nv_bfloat16 d_WcT[3*Cc*Cc];   // combined weights bf16, K-major [sel][k][n]
__device__ __nv_bfloat16 d_outwT[Cc*Cc];   // out_w bf16 K-major [k][n]
__device__ float  d_poskk[H2c*Cc];         // pos_b projected through combined K weights (+bias)
__device__ float  d_posvv[H2c*Cc];

__device__ __forceinline__ unsigned sptr(const void* p) {
    return (unsigned)__cvta_generic_to_shared(p);
}

#define LDMX4(r0,r1,r2,r3,addr) \
    asm volatile("ldmatrix.sync.aligned.m8n8.x4.shared.b16 {%0,%1,%2,%3},[%4];" \
        : "=r"(r0),"=r"(r1),"=r"(r2),"=r"(r3) : "r"(addr))
#define LDMX4T(r0,r1,r2,r3,addr) \
    asm volatile("ldmatrix.sync.aligned.m8n8.x4.trans.shared.b16 {%0,%1,%2,%3},[%4];" \
        : "=r"(r0),"=r"(r1),"=r"(r2),"=r"(r3) : "r"(addr))
#define MMABF16(c0,c1,c2,c3,a0,a1,a2,a3,b0,b1) \
    asm volatile("mma.sync.aligned.m16n8k16.row.col.f32.bf16.bf16.f32 " \
        "{%0,%1,%2,%3},{%4,%5,%6,%7},{%8,%9},{%0,%1,%2,%3};" \
        : "+f"(c0),"+f"(c1),"+f"(c2),"+f"(c3) \
        : "r"(a0),"r"(a1),"r"(a2),"r"(a3),"r"(b0),"r"(b1))

// ---------------- coords for BOTH passes ----------------
__global__ void k_coords_all(const float* __restrict__ rots, const float* __restrict__ fxs,
                             const float* __restrict__ cxs) {
    int p = blockIdx.x * blockDim.x + threadIdx.x;
    int ji = blockIdx.y;
    if (p >= NPTS) return;
    int j = ji * 3;  // cams 0 and 3
    int r = p / W2c, w = p % W2c;
    float fx = fxs[j], cx = cxs[j];
    float cth = rots[j * 9 + 0];
    float sth = rots[j * 9 + 3];
    float ang = atanf((w * 2.0f + 1.0f - cx) / fx);
    float cA = cosf(ang), sA = sinf(ang);
    float ca = sth * cA - cth * sA;
    float sa = cth * cA + sth * sA;
    float rmax = sqrtf(64.f * 64.f + 64.f * 64.f);
    float rad = ((float)r / 127.0f) * rmax;
    float x = 64.f + rad * ca;
    float y = 64.f - rad * sa;
    float xc = fminf(fmaxf(x, 0.f), 127.f);
    float yc = fminf(fmaxf(y, 0.f), 127.f);
    float x0 = floorf(xc), y0 = floorf(yc);
    float x1 = fminf(x0 + 1.f, 127.f), y1 = fminf(y0 + 1.f, 127.f);
    int x0i = (int)x0, x1i = (int)x1, y0i = (int)y0, y1i = (int)y1;
    int q = ji * NPTS + p;
    d_gidx[q] = make_int4(y0i * Ww + x0i, y0i * Ww + x1i, y1i * Ww + x0i, y1i * Ww + x1i);
    d_wxy[q]  = make_float2(xc - x0, yc - y0);
    int xi = (int)fminf(fmaxf(rintf(x), 0.f), 127.f);
    int yi = (int)fminf(fmaxf(rintf(y), 0.f), 127.f);
    d_sidx[q] = yi * Ww + xi;
}

// ---------------- input transpose: (C,H,W) -> (HW, C) ----------------
__global__ void k_transpose_in(const float* __restrict__ a) {
    __shared__ float tile[32][33];
    int hw0 = blockIdx.x * 32;
    int c0  = blockIdx.y * 32;
    for (int i = threadIdx.y; i < 32; i += 8)
        tile[i][threadIdx.x] = a[(size_t)(c0 + i) * HWp + hw0 + threadIdx.x];
    __syncthreads();
    for (int i = threadIdx.y; i < 32; i += 8)
        d_at[(size_t)(hw0 + i) * Cc + c0 + threadIdx.x] = tile[threadIdx.x][i];
}

// ---------------- a_seq = bilinear(a_t) + pos_a  ->  bf16, row = w*128 + r -------------
// 4 points per block; 64 threads per point (float4 channels)
__global__ __launch_bounds__(256) void k_build_aseq(const float* __restrict__ pos_a, int ji) {
    int tx = threadIdx.x & 63;
    int ty = threadIdx.x >> 6;
    int p  = blockIdx.x * 4 + ty;
    int r = p / W2c, w = p % W2c;
    int q = ji * NPTS + p;
    int4 g = d_gidx[q];
    float2 wt = d_wxy[q];
    float w11 = wt.x * wt.y;
    float w01 = wt.x - w11;          // wx*(1-wy)
    float w10 = wt.y - w11;          // (1-wx)*wy
    float w00 = 1.f - wt.x - wt.y + w11;
    float4 v00 = ((const float4*)(d_at + (size_t)g.x * Cc))[tx];
    float4 v01 = ((const float4*)(d_at + (size_t)g.y * Cc))[tx];
    float4 v10 = ((const float4*)(d_at + (size_t)g.z * Cc))[tx];
    float4 v11 = ((const float4*)(d_at + (size_t)g.w * Cc))[tx];
    float4 pa  = ((const float4*)(pos_a + (size_t)r * Cc))[tx];
    float o0 = v00.x * w00 + v01.x * w01 + v10.x * w10 + v11.x * w11 + pa.x;
    float o1 = v00.y * w00 + v01.y * w01 + v10.y * w10 + v11.y * w11 + pa.y;
    float o2 = v00.z * w00 + v01.z * w01 + v10.z * w10 + v11.z * w11 + pa.z;
    float o3 = v00.w * w00 + v01.w * w01 + v10.w * w10 + v11.w * w11 + pa.w;
    int row = w * H1c + r;
    __nv_bfloat162 b0 = {__float2bfloat16_rn(o0), __float2bfloat16_rn(o1)};
    __nv_bfloat162 b1 = {__float2bfloat16_rn(o2), __float2bfloat16_rn(o3)};
    ((__nv_bfloat162*)(d_aseqbf + (size_t)row * Cc))[tx * 2]     = b0;
    ((__nv_bfloat162*)(d_aseqbf + (size_t)row * Cc))[tx * 2 + 1] = b1;
}

// ---------------- combined weights + bias (fused) ----------------
// Wc[sel][n][c] = sum_m in_w[sel*256+n][m] * W{q,k,v}[m][c];  bc[sel][n] = in_b + in_w.b
__global__ void k_combine_wb(const float* __restrict__ Wq, const float* __restrict__ Wk,
                             const float* __restrict__ Wv, const float* __restrict__ in_w,
                             const float* __restrict__ bq, const float* __restrict__ bk,
                             const float* __restrict__ bv, const float* __restrict__ in_b) {
    int n = blockIdx.x, sel = blockIdx.y, c = threadIdx.x;
    const float* W = (sel == 0) ? Wq : ((sel == 1) ? Wk : Wv);
    const float* b = (sel == 0) ? bq : ((sel == 1) ? bk : bv);
    __shared__ float ir[Cc];
    __shared__ float red[8];
    ir[c] = in_w[(size_t)(sel * Cc + n) * Cc + c];
    __syncthreads();
    float s = 0.f;
    #pragma unroll 8
    for (int m = 0; m < Cc; m++) s += ir[m] * W[(size_t)m * Cc + c];
    d_Wc[(size_t)sel * Cc * Cc + (size_t)n * Cc + c] = s;
    // bias reduction
    float pb = ir[c] * b[c];
    #pragma unroll
    for (int o = 16; o > 0; o >>= 1) pb += __shfl_down_sync(0xffffffffu, pb, o);
    if ((c & 31) == 0) red[c >> 5] = pb;
    __syncthreads();
    if (c == 0) {
        float t = 0.f;
        #pragma unroll
        for (int i = 0; i < 8; i++) t += red[i];
        d_bc[sel * Cc + n] = t + in_b[sel * Cc + n];
    }
}

// ---------------- transpose+convert weights [n][k] fp32 -> [k][n] bf16 (4 mats) --------
__global__ void k_w2bt_all(const float* __restrict__ out_w) {
    __shared__ float tile[32][33];
    int z = blockIdx.z;
    const float* src = (z < 3) ? (d_Wc + (size_t)z * Cc * Cc) : out_w;
    __nv_bfloat16* dst = (z < 3) ? (d_WcT + (size_t)z * Cc * Cc) : d_outwT;
    int n0 = blockIdx.x * 32, k0 = blockIdx.y * 32;
    int tx = threadIdx.x;
    for (int i = threadIdx.y; i < 32; i += 8)
        tile[i][tx] = src[(size_t)(n0 + i) * Cc + k0 + tx];
    __syncthreads();
    for (int i = threadIdx.y; i < 32; i += 8)
        dst[(size_t)(k0 + i) * Cc + n0 + tx] = __float2bfloat16_rn(tile[tx][i]);
}

// ---------------- transpose+convert list_b slice [C][M] fp32 -> [M][C] bf16 --------
__global__ void k_b2bt(const float* __restrict__ src) {
    __shared__ float tile[32][33];
    int m0 = blockIdx.x * 32, c0 = blockIdx.y * 32;
    int tx = threadIdx.x;
    for (int i = threadIdx.y; i < 32; i += 8)
        tile[i][tx] = src[(size_t)(c0 + i) * MK + m0 + tx];
    __syncthreads();
    for (int i = threadIdx.y; i < 32; i += 8)
        d_btbf[(size_t)(m0 + i) * Cc + c0 + tx] = __float2bfloat16_rn(tile[tx][i]);
}

// poskk[h][n] = sum_c pos_b[h][c]*WcT_k[c][n] + bck[n]   (and same for V) — coalesced
__global__ void k_pos_proj(const float* __restrict__ pos_b) {
    int h = blockIdx.x, which = blockIdx.y, n = threadIdx.x;
    __shared__ float pb[Cc];
    pb[n] = pos_b[(size_t)h * Cc + n];
    __syncthreads();
    int sel = which + 1;  // 1 = K, 2 = V
    const __nv_bfloat16* W = d_WcT + (size_t)sel * Cc * Cc;
    float s = d_bc[sel * Cc + n];
    #pragma unroll 8
    for (int c = 0; c < Cc; c++) s += pb[c] * __bfloat162float(W[(size_t)c * Cc + n]);
    (which == 0 ? d_poskk : d_posvv)[(size_t)h * Cc + n] = s;
}

// ---------------- tensor-core GEMM: C[M,256] = A[M,256] . BT^T + bias  (bf16 mma) ----
template<int BIASMODE>
__global__ __launch_bounds__(256) void k_mma_gemm(const __nv_bfloat16* __restrict__ A,
                                                  const __nv_bfloat16* __restrict__ BT,
                                                  const float* __restrict__ bias,
                                                  float* __restrict__ C) {
    __shared__ __align__(16) __nv_bfloat16 As[2][128][40];
    __shared__ __align__(16) __nv_bfloat16 Bs[2][32][136];
    int t = threadIdx.x;
    int m0 = blockIdx.x * 128, n0 = blockIdx.y * 128;
    int lane = t & 31, warp = t >> 5;
    int wm = (warp & 3) * 32;
    int wn = (warp >> 2) * 64;

    int am = t >> 2, ak = (t & 3) * 8;
    int bk = t >> 4, bn = (t & 15) * 8;
    const __nv_bfloat16* Ag = A + (size_t)(m0 + am) * Cc + ak;
    const __nv_bfloat16* Bg = BT + (size_t)bk * Cc + n0 + bn;

    float4 va0 = *(const float4*)(Ag);
    float4 va1 = *(const float4*)(Ag + 64 * Cc);
    float4 vb0 = *(const float4*)(Bg);
    float4 vb1 = *(const float4*)(Bg + 16 * Cc);
    *(float4*)&As[0][am][ak]      = va0;
    *(float4*)&As[0][am + 64][ak] = va1;
    *(float4*)&Bs[0][bk][bn]      = vb0;
    *(float4*)&Bs[0][bk + 16][bn] = vb1;
    __syncthreads();

    float acc[2][8][4];
    #pragma unroll
    for (int i = 0; i < 2; i++)
        #pragma unroll
        for (int j = 0; j < 8; j++)
            #pragma unroll
            for (int q = 0; q < 4; q++) acc[i][j][q] = 0.f;

    #pragma unroll 1
    for (int iter = 0; iter < 8; iter++) {
        int buf = iter & 1;
        if (iter < 7) {
            int k0 = (iter + 1) * 32;
            va0 = *(const float4*)(Ag + k0);
            va1 = *(const float4*)(Ag + 64 * Cc + k0);
            vb0 = *(const float4*)(Bg + (size_t)k0 * Cc);
            vb1 = *(const float4*)(Bg + (size_t)(k0 + 16) * Cc);
        }
        #pragma unroll
        for (int kk = 0; kk < 32; kk += 16) {
            unsigned a[2][4], b[8][2];
            #pragma unroll
            for (int i = 0; i < 2; i++) {
                unsigned addr = sptr(&As[buf][wm + i * 16 + (lane & 15)][kk + (lane >> 4) * 8]);
                LDMX4(a[i][0], a[i][1], a[i][2], a[i][3], addr);
            }
            #pragma unroll
            for (int j = 0; j < 4; j++) {
                unsigned addr = sptr(&Bs[buf][kk + (lane & 15)][wn + j * 16 + (lane >> 4) * 8]);
                unsigned r0, r1, r2, r3;
                LDMX4T(r0, r1, r2, r3, addr);
                b[2 * j][0] = r0; b[2 * j][1] = r1;
                b[2 * j + 1][0] = r2; b[2 * j + 1][1] = r3;
            }
            #pragma unroll
            for (int i = 0; i < 2; i++)
                #pragma unroll
                for (int j = 0; j < 8; j++)
                    MMABF16(acc[i][j][0], acc[i][j][1], acc[i][j][2], acc[i][j][3],
                            a[i][0], a[i][1], a[i][2], a[i][3], b[j][0], b[j][1]);
        }
        if (iter < 7) {
            int nb = buf ^ 1;
            *(float4*)&As[nb][am][ak]      = va0;
            *(float4*)&As[nb][am + 64][ak] = va1;
            *(float4*)&Bs[nb][bk][bn]      = vb0;
            *(float4*)&Bs[nb][bk + 16][bn] = vb1;
        }
        __syncthreads();
    }

    #pragma unroll
    for (int i = 0; i < 2; i++) {
        int mrow = m0 + wm + i * 16 + (lane >> 2);
        #pragma unroll
        for (int j = 0; j < 8; j++) {
            int n = n0 + wn + j * 8 + (lane & 3) * 2;
            float b0, b1, b2, b3;
            if (BIASMODE == 0) {
                b0 = bias[n]; b1 = bias[n + 1]; b2 = b0; b3 = b1;
            } else {
                int h0 = mrow / 400, h1 = (mrow + 8) / 400;
                b0 = bias[(size_t)h0 * Cc + n]; b1 = bias[(size_t)h0 * Cc + n + 1];
                b2 = bias[(size_t)h1 * Cc + n]; b3 = bias[(size_t)h1 * Cc + n + 1];
            }
            *(float2*)&C[(size_t)mrow * Cc + n] =
                make_float2(acc[i][j][0] + b0, acc[i][j][1] + b1);
            *(float2*)&C[(size_t)(mrow + 8) * Cc + n] =
                make_float2(acc[i][j][2] + b2, acc[i][j][3] + b3);
        }
    }
}

// ---------------- flash attention: grid (w=400, head=8), 128 threads (one per q-row) ----
__global__ __launch_bounds__(128) void k_attn() {
    int w = blockIdx.x, h = blockIdx.y, r = threadIdx.x;
    __shared__ float Ks[H2c * DHc];
    __shared__ float Vs[H2c * DHc];
    // float4 loads: 2048 floats each = 512 float4; 128 threads x 4
    #pragma unroll
    for (int it = 0; it < 4; it++) {
        int slot = it * 128 + r;            // float4 slot
        int hh = slot >> 3, dq = slot & 7;  // 8 float4 per 32-d row
        size_t src = ((size_t)(hh * W2c + w) * Cc + h * DHc) / 4 + dq;
        ((float4*)Ks)[slot] = ((const float4*)d_kk)[src];
        ((float4*)Vs)[slot] = ((const float4*)d_vv)[src];
    }
    __syncthreads();
    float q[DHc];
    const float4* qp = (const float4*)(d_qq + (size_t)(w * H1c + r) * Cc + h * DHc);
    #pragma unroll
    for (int d = 0; d < 8; d++) ((float4*)q)[d] = qp[d];

    float m_run = -INFINITY, l_run = 0.f;
    float acc[DHc] = {};
    #pragma unroll
    for (int kc = 0; kc < H2c; kc += 16) {
        float sc[16];
        float cmax = -INFINITY;
        #pragma unroll
        for (int k = 0; k < 16; k++) {
            float a = 0.f;
            #pragma unroll
            for (int d = 0; d < DHc; d++) a += q[d] * Ks[(kc + k) * DHc + d];
            a *= 0.17677669529663687f;  // 1/sqrt(32)
            sc[k] = a;
            cmax = fmaxf(cmax, a);
        }
        float nm = fmaxf(m_run, cmax);
        float f = __expf(m_run - nm);   // 0 when m_run = -inf
        l_run *= f;
        #pragma unroll
        for (int d = 0; d < DHc; d++) acc[d] *= f;
        #pragma unroll
        for (int k = 0; k < 16; k++) {
            float p = __expf(sc[k] - nm);
            l_run += p;
            #pragma unroll
            for (int d = 0; d < DHc; d++) acc[d] += p * Vs[(kc + k) * DHc + d];
        }
        m_run = nm;
    }
    float inv = 1.f / l_run;
    __nv_bfloat16* op = d_obf + (size_t)(w * H1c + r) * Cc + h * DHc;
    #pragma unroll
    for (int d = 0; d < DHc; d += 2) {
        __nv_bfloat162 b = {__float2bfloat16_rn(acc[d] * inv),
                            __float2bfloat16_rn(acc[d + 1] * inv)};
        *(__nv_bfloat162*)(op + d) = b;
    }
}

// ---------------- zero rest/cnt ----------------
__global__ void k_zero() {
    size_t i = (size_t)blockIdx.x * 256 + threadIdx.x;
    float4 z = make_float4(0.f, 0.f, 0.f, 0.f);
    ((float4*)d_rest)[i] = z;                 // grid 4096*256 = HWp*Cc/4 exactly
    if (i < HWp / 4) ((float4*)d_cnt)[i] = z;
}

// ---------------- scatter-add into rest / cnt (4 points per block) ----------------
__global__ __launch_bounds__(256) void k_scatter(int ji) {
    int tx = threadIdx.x & 63;
    int ty = threadIdx.x >> 6;
    int p  = blockIdx.x * 4 + ty;
    int r = p / W2c, w = p % W2c;
    int row = w * H1c + r;
    int si = d_sidx[ji * NPTS + p];
    float4 v = ((const float4*)(d_oproj + (size_t)row * Cc))[tx];
    float* dst = d_rest + (size_t)si * Cc + tx * 4;
    atomicAdd(dst + 0, v.x);
    atomicAdd(dst + 1, v.y);
    atomicAdd(dst + 2, v.z);
    atomicAdd(dst + 3, v.w);
    if (tx == 0) atomicAdd(&d_cnt[si], 1.0f);
}

__global__ void k_update() {
    int hw = blockIdx.x, c = threadIdx.x;
    float cnt = d_cnt[hw];
    cnt = (cnt == 0.f) ? 1.f : cnt;
    float e = d_rest[(size_t)hw * Cc + c] / cnt;
    d_enh[(size_t)hw * Cc + c] = e;
    d_at[(size_t)hw * Cc + c] += e;
}

// ---------------- final: out[c][hw] = a_t[hw][c] + enh[hw][c] ----------------
__global__ void k_writeout(float* __restrict__ out) {
    __shared__ float tile[32][33];
    int hw0 = blockIdx.x * 32;
    int c0  = blockIdx.y * 32;
    for (int i = threadIdx.y; i < 32; i += 8) {
        size_t idx = (size_t)(hw0 + i) * Cc + c0 + threadIdx.x;
        tile[i][threadIdx.x] = d_at[idx] + d_enh[idx];
    }
    __syncthreads();
    for (int i = threadIdx.y; i < 32; i += 8)
        out[(size_t)(c0 + i) * HWp + hw0 + threadIdx.x] = tile[threadIdx.x][i];
}

// ---------------- host launcher ----------------
extern "C" void kernel_launch(void* const* d_in, const int* in_sizes, int n_in,
                              void* d_out, int out_size) {
    const float* list_a = (const float*)d_in[0];
    const float* list_b = (const float*)d_in[1];
    const float* rots   = (const float*)d_in[3];
    const float* fxs    = (const float*)d_in[5];
    const float* cxs    = (const float*)d_in[6];
    const float* pos_a  = (const float*)d_in[7];
    const float* pos_b  = (const float*)d_in[8];
    const float* Wq     = (const float*)d_in[9];
    const float* bq     = (const float*)d_in[10];
    const float* Wk     = (const float*)d_in[11];
    const float* bk     = (const float*)d_in[12];
    const float* Wv     = (const float*)d_in[13];
    const float* bv     = (const float*)d_in[14];
    const float* in_w   = (const float*)d_in[15];
    const float* in_b   = (const float*)d_in[16];
    const float* out_w  = (const float*)d_in[17];
    const float* out_b  = (const float*)d_in[18];
    float* out = (float*)d_out;

    float *p_bc, *p_poskk, *p_posvv, *p_qq, *p_kk, *p_vv, *p_oproj;
    __nv_bfloat16 *p_aseqbf, *p_btbf, *p_obf, *p_WcT, *p_outwT;
    cudaGetSymbolAddress((void**)&p_bc,     d_bc);
    cudaGetSymbolAddress((void**)&p_poskk,  d_poskk);
    cudaGetSymbolAddress((void**)&p_posvv,  d_posvv);
    cudaGetSymbolAddress((void**)&p_qq,     d_qq);
    cudaGetSymbolAddress((void**)&p_kk,     d_kk);
    cudaGetSymbolAddress((void**)&p_vv,     d_vv);
    cudaGetSymbolAddress((void**)&p_oproj,  d_oproj);
    cudaGetSymbolAddress((void**)&p_aseqbf, d_aseqbf);
    cudaGetSymbolAddress((void**)&p_btbf,   d_btbf);
    cudaGetSymbolAddress((void**)&p_obf,    d_obf);
    cudaGetSymbolAddress((void**)&p_WcT,    d_WcT);
    cudaGetSymbolAddress((void**)&p_outwT,  d_outwT);

    // launches 0-4 (init) — ordered so launch index 5 is k_mma_gemm(qq) for ncu -s 5
    k_coords_all<<<dim3((NPTS + 255) / 256, 2), 256>>>(rots, fxs, cxs);        // 0
    k_transpose_in<<<dim3(HWp / 32, Cc / 32), dim3(32, 8)>>>(list_a);          // 1
    k_build_aseq<<<NPTS / 4, 256>>>(pos_a, 0);                                 // 2
    k_combine_wb<<<dim3(Cc, 3), Cc>>>(Wq, Wk, Wv, in_w, bq, bk, bv, in_b);     // 3
    k_w2bt_all<<<dim3(8, 8, 4), dim3(32, 8)>>>(out_w);                         // 4
    k_mma_gemm<0><<<dim3(MQ / 128, 2), 256>>>(p_aseqbf, p_WcT, p_bc, p_qq);    // 5 <- profiled
    k_pos_proj<<<dim3(H2c, 2), Cc>>>(pos_b);                                   // 6

    for (int ji = 0; ji < 2; ji++) {
        int j = ji * 3;
        if (ji == 1) {
            k_build_aseq<<<NPTS / 4, 256>>>(pos_a, 1);
            k_mma_gemm<0><<<dim3(MQ / 128, 2), 256>>>(p_aseqbf, p_WcT, p_bc, p_qq);
        }
        k_b2bt<<<dim3(MK / 32, Cc / 32), dim3(32, 8)>>>(list_b + (size_t)j * Cc * MK);
        k_mma_gemm<1><<<dim3(MK / 128, 2), 256>>>(p_btbf, p_WcT + Cc * Cc,     p_poskk, p_kk);
        k_mma_gemm<1><<<dim3(MK / 128, 2), 256>>>(p_btbf, p_WcT + 2 * Cc * Cc, p_posvv, p_vv);
        k_attn<<<dim3(W2c, 8), 128>>>();
        k_mma_gemm<0><<<dim3(MQ / 128, 2), 256>>>(p_obf, p_outwT, out_b, p_oproj);
        k_zero<<<4096, 256>>>();
        k_scatter<<<NPTS / 4, 256>>>(ji);
        k_update<<<HWp, Cc>>>();
    }
    k_writeout<<<dim3(HWp / 32, Cc / 32), dim3(32, 8)>>>(out);
}

// round 4
// speedup vs baseline: 3.2567x; 1.1835x over previous
#include <cuda_runtime.h>
#include <cuda_bf16.h>
#include <math.h>

// ---------------- problem constants ----------------
#define Cc    256
#define HWp   16384      // 128*128
#define Ww    128
#define H1c   128
#define H2c   64
#define W2c   400
#define NPTS  (H1c*W2c)  // 51200
#define MQ    NPTS
#define MK    (H2c*W2c)  // 25600
#define DHc   32

// ---------------- scratch (device globals; no runtime alloc) ----------------
__device__ float  d_at[HWp*Cc];             // working image, HWC layout
__device__ __nv_bfloat16 d_aseqbf[MQ*Cc];   // bilinear-sampled query sequence (+pos_a)
__device__ __nv_bfloat16 d_qqbf[MQ*Cc];
__device__ __nv_bfloat16 d_kkbf[MK*Cc];
__device__ __nv_bfloat16 d_vvbf[MK*Cc];
__device__ __nv_bfloat16 d_obf[MQ*Cc];      // attention output
__device__ float  d_rest[HWp*Cc];
__device__ float  d_cnt[HWp];
__device__ int4   d_gidx[2*NPTS];
__device__ float2 d_wxy[2*NPTS];
__device__ int    d_sidx[2*NPTS];
__device__ float  d_Wc[3*Cc*Cc];            // combined q/k/v weights fp32 [sel][n][k]
__device__ float  d_bc[3*Cc];               // combined biases
__device__ __nv_bfloat16 d_WcT[3*Cc*Cc];    // combined weights bf16, K-major [sel][k][n]
__device__ __nv_bfloat16 d_outwT[Cc*Cc];    // out_w bf16 K-major [k][n]
__device__ float  d_poskk[H2c*Cc];
__device__ float  d_posvv[H2c*Cc];

__device__ __forceinline__ unsigned sptr(const void* p) {
    return (unsigned)__cvta_generic_to_shared(p);
}
__device__ __forceinline__ unsigned bf2u(float a, float b) {
    __nv_bfloat162 t = __floats2bfloat162_rn(a, b);
    return *(unsigned*)&t;
}
__device__ __forceinline__ void bf8_to_f(uint4 v, float* d) {
    const __nv_bfloat162* p = (const __nv_bfloat162*)&v;
    #pragma unroll
    for (int i = 0; i < 4; i++) {
        float2 f = __bfloat1622float2(p[i]);
        d[2 * i] = f.x; d[2 * i + 1] = f.y;
    }
}

#define LDMX4(r0,r1,r2,r3,addr) \
    asm volatile("ldmatrix.sync.aligned.m8n8.x4.shared.b16 {%0,%1,%2,%3},[%4];" \
        : "=r"(r0),"=r"(r1),"=r"(r2),"=r"(r3) : "r"(addr))
#define LDMX4T(r0,r1,r2,r3,addr) \
    asm volatile("ldmatrix.sync.aligned.m8n8.x4.trans.shared.b16 {%0,%1,%2,%3},[%4];" \
        : "=r"(r0),"=r"(r1),"=r"(r2),"=r"(r3) : "r"(addr))
#define MMABF16(c0,c1,c2,c3,a0,a1,a2,a3,b0,b1) \
    asm volatile("mma.sync.aligned.m16n8k16.row.col.f32.bf16.bf16.f32 " \
        "{%0,%1,%2,%3},{%4,%5,%6,%7},{%8,%9},{%0,%1,%2,%3};" \
        : "+f"(c0),"+f"(c1),"+f"(c2),"+f"(c3) \
        : "r"(a0),"r"(a1),"r"(a2),"r"(a3),"r"(b0),"r"(b1))

// ---------------- zero rest/cnt ----------------
__global__ void k_zero() {
    size_t i = (size_t)blockIdx.x * 256 + threadIdx.x;
    float4 z = make_float4(0.f, 0.f, 0.f, 0.f);
    ((float4*)d_rest)[i] = z;
    if (i < HWp / 4) ((float4*)d_cnt)[i] = z;
}

// ---------------- coords for BOTH passes ----------------
__global__ void k_coords_all(const float* __restrict__ rots, const float* __restrict__ fxs,
                             const float* __restrict__ cxs) {
    int p = blockIdx.x * blockDim.x + threadIdx.x;
    int ji = blockIdx.y;
    if (p >= NPTS) return;
    int j = ji * 3;  // cams 0 and 3
    int r = p / W2c, w = p % W2c;
    float fx = fxs[j], cx = cxs[j];
    float cth = rots[j * 9 + 0];
    float sth = rots[j * 9 + 3];
    float ang = atanf((w * 2.0f + 1.0f - cx) / fx);
    float cA = cosf(ang), sA = sinf(ang);
    float ca = sth * cA - cth * sA;
    float sa = cth * cA + sth * sA;
    float rmax = sqrtf(64.f * 64.f + 64.f * 64.f);
    float rad = ((float)r / 127.0f) * rmax;
    float x = 64.f + rad * ca;
    float y = 64.f - rad * sa;
    float xc = fminf(fmaxf(x, 0.f), 127.f);
    float yc = fminf(fmaxf(y, 0.f), 127.f);
    float x0 = floorf(xc), y0 = floorf(yc);
    float x1 = fminf(x0 + 1.f, 127.f), y1 = fminf(y0 + 1.f, 127.f);
    int x0i = (int)x0, x1i = (int)x1, y0i = (int)y0, y1i = (int)y1;
    int q = ji * NPTS + p;
    d_gidx[q] = make_int4(y0i * Ww + x0i, y0i * Ww + x1i, y1i * Ww + x0i, y1i * Ww + x1i);
    d_wxy[q]  = make_float2(xc - x0, yc - y0);
    int xi = (int)fminf(fmaxf(rintf(x), 0.f), 127.f);
    int yi = (int)fminf(fmaxf(rintf(y), 0.f), 127.f);
    d_sidx[q] = yi * Ww + xi;
}

// ---------------- input transpose: (C,H,W) -> (HW, C) ----------------
__global__ void k_transpose_in(const float* __restrict__ a) {
    __shared__ float tile[32][33];
    int hw0 = blockIdx.x * 32;
    int c0  = blockIdx.y * 32;
    for (int i = threadIdx.y; i < 32; i += 8)
        tile[i][threadIdx.x] = a[(size_t)(c0 + i) * HWp + hw0 + threadIdx.x];
    __syncthreads();
    for (int i = threadIdx.y; i < 32; i += 8)
        d_at[(size_t)(hw0 + i) * Cc + c0 + threadIdx.x] = tile[threadIdx.x][i];
}

// ---------------- combined weights + bias (fused) ----------------
__global__ void k_combine_wb(const float* __restrict__ Wq, const float* __restrict__ Wk,
                             const float* __restrict__ Wv, const float* __restrict__ in_w,
                             const float* __restrict__ bq, const float* __restrict__ bk,
                             const float* __restrict__ bv, const float* __restrict__ in_b) {
    int n = blockIdx.x, sel = blockIdx.y, c = threadIdx.x;
    const float* W = (sel == 0) ? Wq : ((sel == 1) ? Wk : Wv);
    const float* b = (sel == 0) ? bq : ((sel == 1) ? bk : bv);
    __shared__ float ir[Cc];
    __shared__ float red[8];
    ir[c] = in_w[(size_t)(sel * Cc + n) * Cc + c];
    __syncthreads();
    float s = 0.f;
    #pragma unroll 8
    for (int m = 0; m < Cc; m++) s += ir[m] * W[(size_t)m * Cc + c];
    d_Wc[(size_t)sel * Cc * Cc + (size_t)n * Cc + c] = s;
    float pb = ir[c] * b[c];
    #pragma unroll
    for (int o = 16; o > 0; o >>= 1) pb += __shfl_down_sync(0xffffffffu, pb, o);
    if ((c & 31) == 0) red[c >> 5] = pb;
    __syncthreads();
    if (c == 0) {
        float t = 0.f;
        #pragma unroll
        for (int i = 0; i < 8; i++) t += red[i];
        d_bc[sel * Cc + n] = t + in_b[sel * Cc + n];
    }
}

// ---------------- transpose+convert weights [n][k] fp32 -> [k][n] bf16 (4 mats) --------
__global__ void k_w2bt_all(const float* __restrict__ out_w) {
    __shared__ float tile[32][33];
    int z = blockIdx.z;
    const float* src = (z < 3) ? (d_Wc + (size_t)z * Cc * Cc) : out_w;
    __nv_bfloat16* dst = (z < 3) ? (d_WcT + (size_t)z * Cc * Cc) : d_outwT;
    int n0 = blockIdx.x * 32, k0 = blockIdx.y * 32;
    int tx = threadIdx.x;
    for (int i = threadIdx.y; i < 32; i += 8)
        tile[i][tx] = src[(size_t)(n0 + i) * Cc + k0 + tx];
    __syncthreads();
    for (int i = threadIdx.y; i < 32; i += 8)
        dst[(size_t)(k0 + i) * Cc + n0 + tx] = __float2bfloat16_rn(tile[tx][i]);
}

// ---------------- a_seq = bilinear(a_t) + pos_a  ->  bf16, row = w*128 + r -------------
__global__ __launch_bounds__(256) void k_build_aseq(const float* __restrict__ pos_a, int ji) {
    int tx = threadIdx.x & 63;
    int ty = threadIdx.x >> 6;
    int p  = blockIdx.x * 4 + ty;
    int r = p / W2c, w = p % W2c;
    int q = ji * NPTS + p;
    int4 g = d_gidx[q];
    float2 wt = d_wxy[q];
    float w11 = wt.x * wt.y;
    float w01 = wt.x - w11;
    float w10 = wt.y - w11;
    float w00 = 1.f - wt.x - wt.y + w11;
    float4 v00 = ((const float4*)(d_at + (size_t)g.x * Cc))[tx];
    float4 v01 = ((const float4*)(d_at + (size_t)g.y * Cc))[tx];
    float4 v10 = ((const float4*)(d_at + (size_t)g.z * Cc))[tx];
    float4 v11 = ((const float4*)(d_at + (size_t)g.w * Cc))[tx];
    float4 pa  = ((const float4*)(pos_a + (size_t)r * Cc))[tx];
    float o0 = v00.x * w00 + v01.x * w01 + v10.x * w10 + v11.x * w11 + pa.x;
    float o1 = v00.y * w00 + v01.y * w01 + v10.y * w10 + v11.y * w11 + pa.y;
    float o2 = v00.z * w00 + v01.z * w01 + v10.z * w10 + v11.z * w11 + pa.z;
    float o3 = v00.w * w00 + v01.w * w01 + v10.w * w10 + v11.w * w11 + pa.w;
    int row = w * H1c + r;
    uint2 u = {bf2u(o0, o1), bf2u(o2, o3)};
    *(uint2*)(d_aseqbf + (size_t)row * Cc + tx * 4) = u;
}

// poskk[h][n] = sum_c pos_b[h][c]*WcT_k[c][n] + bck[n]   (and same for V)
__global__ void k_pos_proj(const float* __restrict__ pos_b) {
    int h = blockIdx.x, which = blockIdx.y, n = threadIdx.x;
    __shared__ float pb[Cc];
    pb[n] = pos_b[(size_t)h * Cc + n];
    __syncthreads();
    int sel = which + 1;
    const __nv_bfloat16* W = d_WcT + (size_t)sel * Cc * Cc;
    float s = d_bc[sel * Cc + n];
    #pragma unroll 8
    for (int c = 0; c < Cc; c++) s += pb[c] * __bfloat162float(W[(size_t)c * Cc + n]);
    (which == 0 ? d_poskk : d_posvv)[(size_t)h * Cc + n] = s;
}

// ---------------- tensor-core GEMM ----------------
// AMODE 0: A bf16 row-major [M][256].  AMODE 1: A fp32 K-major [256][lda] (converted).
// OUTMODE 1: bf16 store.  OUTMODE 2: fp32 atomic scatter into d_rest via d_sidx.
// BIASMODE 0: bias[n].   BIASMODE 1: bias[(m/400)*256 + n].
template<int AMODE, int OUTMODE, int BIASMODE>
__global__ __launch_bounds__(256) void k_mma_gemm(const void* __restrict__ Ap,
                                                  const __nv_bfloat16* __restrict__ BT,
                                                  const float* __restrict__ bias,
                                                  __nv_bfloat16* __restrict__ Cbf,
                                                  int lda, int sidx_off) {
    // AMODE0 layout: [m][40] (128*40=5120); AMODE1 layout: [k][136] (32*136=4352)
    __shared__ __align__(16) __nv_bfloat16 Asm[2][5120];
    __shared__ __align__(16) __nv_bfloat16 Bsm[2][32 * 136];
    int t = threadIdx.x, lane = t & 31, warp = t >> 5;
    int m0 = blockIdx.x * 128, n0 = blockIdx.y * 128;
    int wm = (warp & 3) * 32;
    int wn = (warp >> 2) * 64;

    const __nv_bfloat16* Abf = (const __nv_bfloat16*)Ap;
    const float* Afp = (const float*)Ap;
    int am = t >> 2, ak = (t & 3) * 8;      // AMODE0
    int a1k = t >> 3, a1m = (t & 7) * 16;   // AMODE1
    int bk = t >> 4, bn = (t & 15) * 8;

    float4 pa0, pa1, pa2, pa3, pb0, pb1;

    #define GLOAD(k0) do { \
        if (AMODE == 0) { \
            pa0 = *(const float4*)(Abf + (size_t)(m0 + am) * Cc + (k0) + ak); \
            pa1 = *(const float4*)(Abf + (size_t)(m0 + am + 64) * Cc + (k0) + ak); \
        } else { \
            const float4* g = (const float4*)(Afp + (size_t)((k0) + a1k) * lda + m0 + a1m); \
            pa0 = g[0]; pa1 = g[1]; pa2 = g[2]; pa3 = g[3]; \
        } \
        pb0 = *(const float4*)(BT + (size_t)((k0) + bk) * Cc + n0 + bn); \
        pb1 = *(const float4*)(BT + (size_t)((k0) + bk + 16) * Cc + n0 + bn); \
    } while (0)

    #define SSTORE(buf) do { \
        if (AMODE == 0) { \
            *(float4*)&Asm[buf][am * 40 + ak] = pa0; \
            *(float4*)&Asm[buf][(am + 64) * 40 + ak] = pa1; \
        } else { \
            uint4 u0 = {bf2u(pa0.x, pa0.y), bf2u(pa0.z, pa0.w), \
                        bf2u(pa1.x, pa1.y), bf2u(pa1.z, pa1.w)}; \
            uint4 u1 = {bf2u(pa2.x, pa2.y), bf2u(pa2.z, pa2.w), \
                        bf2u(pa3.x, pa3.y), bf2u(pa3.z, pa3.w)}; \
            *(uint4*)&Asm[buf][a1k * 136 + a1m] = u0; \
            *(uint4*)&Asm[buf][a1k * 136 + a1m + 8] = u1; \
        } \
        *(float4*)&Bsm[buf][bk * 136 + bn] = pb0; \
        *(float4*)&Bsm[buf][(bk + 16) * 136 + bn] = pb1; \
    } while (0)

    GLOAD(0);
    SSTORE(0);
    __syncthreads();

    float acc[2][8][4];
    #pragma unroll
    for (int i = 0; i < 2; i++)
        #pragma unroll
        for (int j = 0; j < 8; j++)
            #pragma unroll
            for (int q = 0; q < 4; q++) acc[i][j][q] = 0.f;

    #pragma unroll 1
    for (int iter = 0; iter < 8; iter++) {
        int buf = iter & 1;
        if (iter < 7) GLOAD((iter + 1) * 32);
        #pragma unroll
        for (int kk = 0; kk < 32; kk += 16) {
            unsigned a[2][4], b[8][2];
            #pragma unroll
            for (int i = 0; i < 2; i++) {
                if (AMODE == 0) {
                    unsigned addr = sptr(&Asm[buf][(wm + i * 16 + (lane & 15)) * 40 + kk + (lane >> 4) * 8]);
                    LDMX4(a[i][0], a[i][1], a[i][2], a[i][3], addr);
                } else {
                    unsigned addr = sptr(&Asm[buf][(kk + (lane & 15)) * 136 + wm + i * 16 + (lane >> 4) * 8]);
                    unsigned r0, r1, r2, r3;
                    LDMX4T(r0, r1, r2, r3, addr);
                    a[i][0] = r0; a[i][1] = r2; a[i][2] = r1; a[i][3] = r3;
                }
            }
            #pragma unroll
            for (int j = 0; j < 4; j++) {
                unsigned addr = sptr(&Bsm[buf][(kk + (lane & 15)) * 136 + wn + j * 16 + (lane >> 4) * 8]);
                unsigned r0, r1, r2, r3;
                LDMX4T(r0, r1, r2, r3, addr);
                b[2 * j][0] = r0; b[2 * j][1] = r1;
                b[2 * j + 1][0] = r2; b[2 * j + 1][1] = r3;
            }
            #pragma unroll
            for (int i = 0; i < 2; i++)
                #pragma unroll
                for (int j = 0; j < 8; j++)
                    MMABF16(acc[i][j][0], acc[i][j][1], acc[i][j][2], acc[i][j][3],
                            a[i][0], a[i][1], a[i][2], a[i][3], b[j][0], b[j][1]);
        }
        if (iter < 7) SSTORE(buf ^ 1);
        __syncthreads();
    }

    #pragma unroll
    for (int i = 0; i < 2; i++) {
        int mrow = m0 + wm + i * 16 + (lane >> 2);
        #pragma unroll
        for (int j = 0; j < 8; j++) {
            int n = n0 + wn + j * 8 + (lane & 3) * 2;
            float b0, b1, b2, b3;
            if (BIASMODE == 0) {
                b0 = bias[n]; b1 = bias[n + 1]; b2 = b0; b3 = b1;
            } else {
                int h0 = mrow / 400, h1 = (mrow + 8) / 400;
                b0 = bias[(size_t)h0 * Cc + n]; b1 = bias[(size_t)h0 * Cc + n + 1];
                b2 = bias[(size_t)h1 * Cc + n]; b3 = bias[(size_t)h1 * Cc + n + 1];
            }
            float v00 = acc[i][j][0] + b0, v01 = acc[i][j][1] + b1;
            float v10 = acc[i][j][2] + b2, v11 = acc[i][j][3] + b3;
            if (OUTMODE == 1) {
                *(__nv_bfloat162*)(Cbf + (size_t)mrow * Cc + n) = __floats2bfloat162_rn(v00, v01);
                *(__nv_bfloat162*)(Cbf + (size_t)(mrow + 8) * Cc + n) = __floats2bfloat162_rn(v10, v11);
            } else {
                int p0 = (mrow & 127) * W2c + (mrow >> 7);
                int p1 = ((mrow + 8) & 127) * W2c + ((mrow + 8) >> 7);
                int s0 = d_sidx[sidx_off + p0];
                int s1 = d_sidx[sidx_off + p1];
                atomicAdd(&d_rest[(size_t)s0 * Cc + n],     v00);
                atomicAdd(&d_rest[(size_t)s0 * Cc + n + 1], v01);
                atomicAdd(&d_rest[(size_t)s1 * Cc + n],     v10);
                atomicAdd(&d_rest[(size_t)s1 * Cc + n + 1], v11);
            }
        }
    }
    #undef GLOAD
    #undef SSTORE
}

// ---------------- flash attention: grid (w=400, head=8), 128 threads ----------------
__global__ __launch_bounds__(128) void k_attn() {
    int w = blockIdx.x, h = blockIdx.y, r = threadIdx.x;
    __shared__ float Ks[H2c * DHc];
    __shared__ float Vs[H2c * DHc];
    #pragma unroll
    for (int it = 0; it < 2; it++) {
        int g = it * 128 + r;               // 256 groups of 8 elems
        int hh = g >> 2, dq = (g & 3) * 8;
        size_t src = ((size_t)(hh * W2c + w) * Cc + h * DHc + dq) >> 3;  // uint4 index
        bf8_to_f(((const uint4*)d_kkbf)[src], Ks + g * 8);
        bf8_to_f(((const uint4*)d_vvbf)[src], Vs + g * 8);
    }
    __syncthreads();
    float q[DHc];
    const uint4* qp = (const uint4*)(d_qqbf + (size_t)(w * H1c + r) * Cc + h * DHc);
    #pragma unroll
    for (int d = 0; d < 4; d++) bf8_to_f(qp[d], q + d * 8);

    float m_run = -INFINITY, l_run = 0.f;
    float acc[DHc] = {};
    #pragma unroll
    for (int kc = 0; kc < H2c; kc += 16) {
        float sc[16];
        float cmax = -INFINITY;
        #pragma unroll
        for (int k = 0; k < 16; k++) {
            float a = 0.f;
            #pragma unroll
            for (int d = 0; d < DHc; d++) a += q[d] * Ks[(kc + k) * DHc + d];
            a *= 0.17677669529663687f;  // 1/sqrt(32)
            sc[k] = a;
            cmax = fmaxf(cmax, a);
        }
        float nm = fmaxf(m_run, cmax);
        float f = __expf(m_run - nm);
        l_run *= f;
        #pragma unroll
        for (int d = 0; d < DHc; d++) acc[d] *= f;
        #pragma unroll
        for (int k = 0; k < 16; k++) {
            float p = __expf(sc[k] - nm);
            l_run += p;
            #pragma unroll
            for (int d = 0; d < DHc; d++) acc[d] += p * Vs[(kc + k) * DHc + d];
        }
        m_run = nm;
    }
    float inv = 1.f / l_run;
    __nv_bfloat16* op = d_obf + (size_t)(w * H1c + r) * Cc + h * DHc;
    #pragma unroll
    for (int d = 0; d < DHc; d += 2)
        *(__nv_bfloat162*)(op + d) = __floats2bfloat162_rn(acc[d] * inv, acc[d + 1] * inv);
}

// ---------------- count scatter hits ----------------
__global__ void k_cnt(int ji) {
    int p = blockIdx.x * 256 + threadIdx.x;
    atomicAdd(&d_cnt[d_sidx[ji * NPTS + p]], 1.0f);
}

// ---------------- update (pass 1): at += rest/cnt, then rezero rest/cnt ----------------
__global__ void k_update() {
    int hw = blockIdx.x, c = threadIdx.x;
    float cnt = d_cnt[hw];
    cnt = (cnt == 0.f) ? 1.f : cnt;
    size_t idx = (size_t)hw * Cc + c;
    d_at[idx] += d_rest[idx] / cnt;
    d_rest[idx] = 0.f;
    if (c == 0) d_cnt[hw] = 0.f;
}

// ---------------- final: out[c][hw] = at[hw][c] + 2*rest[hw][c]/cnt[hw] ----------------
__global__ void k_writeout(float* __restrict__ out) {
    __shared__ float tile[32][33];
    int hw0 = blockIdx.x * 32;
    int c0  = blockIdx.y * 32;
    int tx = threadIdx.x;
    for (int i = threadIdx.y; i < 32; i += 8) {
        float cnt = d_cnt[hw0 + i];
        cnt = (cnt == 0.f) ? 1.f : cnt;
        size_t idx = (size_t)(hw0 + i) * Cc + c0 + tx;
        tile[i][tx] = d_at[idx] + 2.f * d_rest[idx] / cnt;
    }
    __syncthreads();
    for (int i = threadIdx.y; i < 32; i += 8)
        out[(size_t)(c0 + i) * HWp + hw0 + tx] = tile[tx][i];
}

// ---------------- host launcher ----------------
extern "C" void kernel_launch(void* const* d_in, const int* in_sizes, int n_in,
                              void* d_out, int out_size) {
    const float* list_a = (const float*)d_in[0];
    const float* list_b = (const float*)d_in[1];
    const float* rots   = (const float*)d_in[3];
    const float* fxs    = (const float*)d_in[5];
    const float* cxs    = (const float*)d_in[6];
    const float* pos_a  = (const float*)d_in[7];
    const float* pos_b  = (const float*)d_in[8];
    const float* Wq     = (const float*)d_in[9];
    const float* bq     = (const float*)d_in[10];
    const float* Wk     = (const float*)d_in[11];
    const float* bk     = (const float*)d_in[12];
    const float* Wv     = (const float*)d_in[13];
    const float* bv     = (const float*)d_in[14];
    const float* in_w   = (const float*)d_in[15];
    const float* in_b   = (const float*)d_in[16];
    const float* out_w  = (const float*)d_in[17];
    const float* out_b  = (const float*)d_in[18];
    float* out = (float*)d_out;

    float *p_bc, *p_poskk, *p_posvv;
    __nv_bfloat16 *p_aseqbf, *p_qqbf, *p_kkbf, *p_vvbf, *p_obf, *p_WcT, *p_outwT;
    cudaGetSymbolAddress((void**)&p_bc,     d_bc);
    cudaGetSymbolAddress((void**)&p_poskk,  d_poskk);
    cudaGetSymbolAddress((void**)&p_posvv,  d_posvv);
    cudaGetSymbolAddress((void**)&p_aseqbf, d_aseqbf);
    cudaGetSymbolAddress((void**)&p_qqbf,   d_qqbf);
    cudaGetSymbolAddress((void**)&p_kkbf,   d_kkbf);
    cudaGetSymbolAddress((void**)&p_vvbf,   d_vvbf);
    cudaGetSymbolAddress((void**)&p_obf,    d_obf);
    cudaGetSymbolAddress((void**)&p_WcT,    d_WcT);
    cudaGetSymbolAddress((void**)&p_outwT,  d_outwT);

    k_zero<<<4096, 256>>>();
    k_coords_all<<<dim3((NPTS + 255) / 256, 2), 256>>>(rots, fxs, cxs);
    k_transpose_in<<<dim3(HWp / 32, Cc / 32), dim3(32, 8)>>>(list_a);
    k_combine_wb<<<dim3(Cc, 3), Cc>>>(Wq, Wk, Wv, in_w, bq, bk, bv, in_b);
    k_w2bt_all<<<dim3(8, 8, 4), dim3(32, 8)>>>(out_w);
    k_build_aseq<<<NPTS / 4, 256>>>(pos_a, 0);
    k_pos_proj<<<dim3(H2c, 2), Cc>>>(pos_b);

    for (int ji = 0; ji < 2; ji++) {
        int j = ji * 3;
        if (ji == 1) k_build_aseq<<<NPTS / 4, 256>>>(pos_a, 1);
        // qq = a_seq @ Wcq^T + bcq  (bf16 out)
        k_mma_gemm<0, 1, 0><<<dim3(MQ / 128, 2), 256>>>(p_aseqbf, p_WcT, p_bc, p_qqbf, 256, 0);
        // kk/vv directly from fp32 K-major list_b slice (bf16 out)
        const void* bbase = (const void*)(list_b + (size_t)j * Cc * MK);
        k_mma_gemm<1, 1, 1><<<dim3(MK / 128, 2), 256>>>(bbase, p_WcT + Cc * Cc,     p_poskk, p_kkbf, MK, 0);
        k_mma_gemm<1, 1, 1><<<dim3(MK / 128, 2), 256>>>(bbase, p_WcT + 2 * Cc * Cc, p_posvv, p_vvbf, MK, 0);
        // attention
        k_attn<<<dim3(W2c, 8), 128>>>();
        // output projection fused with scatter-add into d_rest
        k_mma_gemm<0, 2, 0><<<dim3(MQ / 128, 2), 256>>>(p_obf, p_outwT, out_b, p_qqbf /*unused*/, 256, ji * NPTS);
        k_cnt<<<NPTS / 256, 256>>>(ji);
        if (ji == 0) k_update<<<HWp, Cc>>>();
    }
    k_writeout<<<dim3(HWp / 32, Cc / 32), dim3(32, 8)>>>(out);
}

// round 7
// speedup vs baseline: 3.3304x; 1.0227x over previous
#include <cuda_runtime.h>
#include <cuda_bf16.h>
#include <math.h>

// ---------------- problem constants ----------------
#define Cc    256
#define HWp   16384      // 128*128
#define Ww    128
#define H1c   128
#define H2c   64
#define W2c   400
#define NPTS  (H1c*W2c)  // 51200
#define MQ    NPTS
#define MK    (H2c*W2c)  // 25600
#define DHc   32

// ---------------- scratch (device globals; no runtime alloc) ----------------
__device__ float  d_at[HWp*Cc];             // working image, HWC layout
__device__ __nv_bfloat16 d_aseqbf[MQ*Cc];
__device__ __nv_bfloat16 d_btbf[MK*Cc];     // list_b slice transposed to [M][K] bf16
__device__ __nv_bfloat16 d_qqbf[MQ*Cc];
__device__ __nv_bfloat16 d_kkbf[MK*Cc];
__device__ __nv_bfloat16 d_vvbf[MK*Cc];
__device__ __nv_bfloat16 d_obf[MQ*Cc];
__device__ float  d_rest[HWp*Cc];
__device__ float  d_cnt[HWp];
__device__ int4   d_gidx[2*NPTS];
__device__ float2 d_wxy[2*NPTS];
__device__ int    d_sidx[2*NPTS];
__device__ float  d_bc[3*Cc];               // combined biases
__device__ __nv_bfloat16 d_WqT[Cc*Cc];      // combined Q weight bf16 K-major [k][n]
__device__ __nv_bfloat16 d_WkvT[Cc*2*Cc];   // stacked K|V weights bf16 K-major [k][512]
__device__ __nv_bfloat16 d_outwT[Cc*Cc];    // out_w bf16 K-major [k][n]
__device__ float  d_poskv[H2c*2*Cc];        // stacked pos bias [h][512] (K|V)

__device__ __forceinline__ unsigned sptr(const void* p) {
    return (unsigned)__cvta_generic_to_shared(p);
}
__device__ __forceinline__ unsigned bf2u(float a, float b) {
    __nv_bfloat162 t = __floats2bfloat162_rn(a, b);
    return *(unsigned*)&t;
}
__device__ __forceinline__ void bf8_to_f(uint4 v, float* d) {
    const __nv_bfloat162* p = (const __nv_bfloat162*)&v;
    #pragma unroll
    for (int i = 0; i < 4; i++) {
        float2 f = __bfloat1622float2(p[i]);
        d[2 * i] = f.x; d[2 * i + 1] = f.y;
    }
}
// -------- packed fp32x2 (Blackwell) --------
__device__ __forceinline__ unsigned long long pk2(float a, float b) {
    unsigned long long r; asm("mov.b64 %0,{%1,%2};" : "=l"(r) : "f"(a), "f"(b)); return r;
}
__device__ __forceinline__ void upk2(unsigned long long v, float& a, float& b) {
    asm("mov.b64 {%0,%1},%2;" : "=f"(a), "=f"(b) : "l"(v));
}
__device__ __forceinline__ unsigned long long fma2(unsigned long long a, unsigned long long b,
                                                   unsigned long long c) {
    unsigned long long d; asm("fma.rn.f32x2 %0,%1,%2,%3;" : "=l"(d) : "l"(a), "l"(b), "l"(c));
    return d;
}
__device__ __forceinline__ unsigned long long mul2(unsigned long long a, unsigned long long b) {
    unsigned long long d; asm("mul.rn.f32x2 %0,%1,%2;" : "=l"(d) : "l"(a), "l"(b));
    return d;
}
// -------- cp.async --------
__device__ __forceinline__ void cp16(unsigned saddr, const void* g) {
    asm volatile("cp.async.ca.shared.global [%0], [%1], 16;" :: "r"(saddr), "l"(g));
}
#define CP_COMMIT() asm volatile("cp.async.commit_group;" ::: "memory")

#define LDMX4(r0,r1,r2,r3,addr) \
    asm volatile("ldmatrix.sync.aligned.m8n8.x4.shared.b16 {%0,%1,%2,%3},[%4];" \
        : "=r"(r0),"=r"(r1),"=r"(r2),"=r"(r3) : "r"(addr))
#define LDMX4T(r0,r1,r2,r3,addr) \
    asm volatile("ldmatrix.sync.aligned.m8n8.x4.trans.shared.b16 {%0,%1,%2,%3},[%4];" \
        : "=r"(r0),"=r"(r1),"=r"(r2),"=r"(r3) : "r"(addr))
#define MMABF16(c0,c1,c2,c3,a0,a1,a2,a3,b0,b1) \
    asm volatile("mma.sync.aligned.m16n8k16.row.col.f32.bf16.bf16.f32 " \
        "{%0,%1,%2,%3},{%4,%5,%6,%7},{%8,%9},{%0,%1,%2,%3};" \
        : "+f"(c0),"+f"(c1),"+f"(c2),"+f"(c3) \
        : "r"(a0),"r"(a1),"r"(a2),"r"(a3),"r"(b0),"r"(b1))

// ---------------- combined weights + bias + bf16 K-major transposes (one kernel) -------
// sel 0..2: Wc_row(n) = in_w[sel*256+n] . W{q,k,v}; write transposed bf16; bias reduce.
// sel 3: transpose out_w -> d_outwT.
__global__ void k_combine_all(const float* __restrict__ Wq, const float* __restrict__ Wk,
                              const float* __restrict__ Wv, const float* __restrict__ in_w,
                              const float* __restrict__ bq, const float* __restrict__ bk,
                              const float* __restrict__ bv, const float* __restrict__ in_b,
                              const float* __restrict__ out_w) {
    int n = blockIdx.x, sel = blockIdx.y, c = threadIdx.x;
    if (sel == 3) {
        d_outwT[(size_t)c * Cc + n] = __float2bfloat16_rn(out_w[(size_t)n * Cc + c]);
        return;
    }
    const float* W = (sel == 0) ? Wq : ((sel == 1) ? Wk : Wv);
    const float* b = (sel == 0) ? bq : ((sel == 1) ? bk : bv);
    __shared__ float ir[Cc];
    __shared__ float red[8];
    ir[c] = in_w[(size_t)(sel * Cc + n) * Cc + c];
    __syncthreads();
    float s = 0.f;
    #pragma unroll 8
    for (int m = 0; m < Cc; m++) s += ir[m] * W[(size_t)m * Cc + c];
    if (sel == 0) d_WqT[(size_t)c * Cc + n] = __float2bfloat16_rn(s);
    else d_WkvT[(size_t)c * 512 + (sel - 1) * Cc + n] = __float2bfloat16_rn(s);
    float pb = ir[c] * b[c];
    #pragma unroll
    for (int o = 16; o > 0; o >>= 1) pb += __shfl_down_sync(0xffffffffu, pb, o);
    if ((c & 31) == 0) red[c >> 5] = pb;
    __syncthreads();
    if (c == 0) {
        float t = 0.f;
        #pragma unroll
        for (int i = 0; i < 8; i++) t += red[i];
        d_bc[sel * Cc + n] = t + in_b[sel * Cc + n];
    }
}

// poskv[h][which*256+n] = sum_c pos_b[h][c]*WkvT[c][which*256+n] + bc[(which+1)*256+n]
__global__ void k_pos_proj(const float* __restrict__ pos_b) {
    int h = blockIdx.x, which = blockIdx.y, n = threadIdx.x;
    __shared__ float pb[Cc];
    pb[n] = pos_b[(size_t)h * Cc + n];
    __syncthreads();
    float s = d_bc[(which + 1) * Cc + n];
    #pragma unroll 8
    for (int c = 0; c < Cc; c++)
        s += pb[c] * __bfloat162float(d_WkvT[(size_t)c * 512 + which * 256 + n]);
    d_poskv[(size_t)h * 512 + which * 256 + n] = s;
}

// ---------------- transpose+convert list_b slice [C][M] fp32 -> [M][C] bf16 ----------
__global__ void k_b2bt(const float* __restrict__ src) {
    __shared__ float tile[32][33];
    int m0 = blockIdx.x * 32, c0 = blockIdx.y * 32;
    int tx = threadIdx.x;
    for (int i = threadIdx.y; i < 32; i += 8)
        tile[i][tx] = src[(size_t)(c0 + i) * MK + m0 + tx];
    __syncthreads();
    for (int i = threadIdx.y; i < 32; i += 8)
        d_btbf[(size_t)(m0 + i) * Cc + c0 + tx] = __float2bfloat16_rn(tile[tx][i]);
}

// ---------------- coords for BOTH passes ----------------
__global__ void k_coords_all(const float* __restrict__ rots, const float* __restrict__ fxs,
                             const float* __restrict__ cxs) {
    int p = blockIdx.x * blockDim.x + threadIdx.x;
    int ji = blockIdx.y;
    if (p >= NPTS) return;
    int j = ji * 3;  // cams 0 and 3
    int r = p / W2c, w = p % W2c;
    float fx = fxs[j], cx = cxs[j];
    float cth = rots[j * 9 + 0];
    float sth = rots[j * 9 + 3];
    float ang = atanf((w * 2.0f + 1.0f - cx) / fx);
    float cA = cosf(ang), sA = sinf(ang);
    float ca = sth * cA - cth * sA;
    float sa = cth * cA + sth * sA;
    float rmax = sqrtf(64.f * 64.f + 64.f * 64.f);
    float rad = ((float)r / 127.0f) * rmax;
    float x = 64.f + rad * ca;
    float y = 64.f - rad * sa;
    float xc = fminf(fmaxf(x, 0.f), 127.f);
    float yc = fminf(fmaxf(y, 0.f), 127.f);
    float x0 = floorf(xc), y0 = floorf(yc);
    float x1 = fminf(x0 + 1.f, 127.f), y1 = fminf(y0 + 1.f, 127.f);
    int x0i = (int)x0, x1i = (int)x1, y0i = (int)y0, y1i = (int)y1;
    int q = ji * NPTS + p;
    d_gidx[q] = make_int4(y0i * Ww + x0i, y0i * Ww + x1i, y1i * Ww + x0i, y1i * Ww + x1i);
    d_wxy[q]  = make_float2(xc - x0, yc - y0);
    int xi = (int)fminf(fmaxf(rintf(x), 0.f), 127.f);
    int yi = (int)fminf(fmaxf(rintf(y), 0.f), 127.f);
    d_sidx[q] = yi * Ww + xi;
}

// ---------------- input transpose: (C,H,W) -> (HW, C) ----------------
__global__ void k_transpose_in(const float* __restrict__ a) {
    __shared__ float tile[32][33];
    int hw0 = blockIdx.x * 32;
    int c0  = blockIdx.y * 32;
    for (int i = threadIdx.y; i < 32; i += 8)
        tile[i][threadIdx.x] = a[(size_t)(c0 + i) * HWp + hw0 + threadIdx.x];
    __syncthreads();
    for (int i = threadIdx.y; i < 32; i += 8)
        d_at[(size_t)(hw0 + i) * Cc + c0 + threadIdx.x] = tile[threadIdx.x][i];
}

// ---------------- a_seq = bilinear(a_t) + pos_a  ->  bf16 ----------------
__global__ __launch_bounds__(256) void k_build_aseq(const float* __restrict__ pos_a, int ji) {
    int tx = threadIdx.x & 63;
    int ty = threadIdx.x >> 6;
    int p  = blockIdx.x * 4 + ty;
    int r = p / W2c, w = p % W2c;
    int q = ji * NPTS + p;
    int4 g = d_gidx[q];
    float2 wt = d_wxy[q];
    float w11 = wt.x * wt.y;
    float w01 = wt.x - w11;
    float w10 = wt.y - w11;
    float w00 = 1.f - wt.x - wt.y + w11;
    float4 v00 = ((const float4*)(d_at + (size_t)g.x * Cc))[tx];
    float4 v01 = ((const float4*)(d_at + (size_t)g.y * Cc))[tx];
    float4 v10 = ((const float4*)(d_at + (size_t)g.z * Cc))[tx];
    float4 v11 = ((const float4*)(d_at + (size_t)g.w * Cc))[tx];
    float4 pa  = ((const float4*)(pos_a + (size_t)r * Cc))[tx];
    float o0 = v00.x * w00 + v01.x * w01 + v10.x * w10 + v11.x * w11 + pa.x;
    float o1 = v00.y * w00 + v01.y * w01 + v10.y * w10 + v11.y * w11 + pa.y;
    float o2 = v00.z * w00 + v01.z * w01 + v10.z * w10 + v11.z * w11 + pa.z;
    float o3 = v00.w * w00 + v01.w * w01 + v10.w * w10 + v11.w * w11 + pa.w;
    int row = w * H1c + r;
    uint2 u = {bf2u(o0, o1), bf2u(o2, o3)};
    *(uint2*)(d_aseqbf + (size_t)row * Cc + tx * 4) = u;
}

// ================= cp.async pipelined bf16 mma GEMM =================
// C[M, gridDim.y*128] = A[M,256] . BT^T + bias
// A bf16 row-major [M][256]; BT bf16 K-major [256][ldb].
// OUTMODE 1: bf16 store; n<256 -> outA else outB (col n&255).
// OUTMODE 2: fp32 atomic scatter into restP via d_sidx.
// BIASMODE 0: bias[n].  BIASMODE 1: bias[(m/400)*biasld + n].
// dyn smem: 3 A stages [128][40] bf16 (10240B each) + 3 B stages [32][136] bf16 (8704B each)
#define GSM_A(st)  ((st) * 10240)
#define GSM_B(st)  (30720 + (st) * 8704)
#define GSM_TOTAL  56832
template<int OUTMODE, int BIASMODE>
__global__ __launch_bounds__(256) void k_mma_gemm(const __nv_bfloat16* __restrict__ A,
                                                  const __nv_bfloat16* __restrict__ BT,
                                                  const float* __restrict__ bias,
                                                  __nv_bfloat16* __restrict__ outA,
                                                  __nv_bfloat16* __restrict__ outB,
                                                  float* __restrict__ restP,
                                                  int ldb, int biasld, int sidx_off) {
    extern __shared__ __align__(16) char gsm[];
    unsigned sbase = sptr(gsm);
    int t = threadIdx.x, lane = t & 31, warp = t >> 5;
    int m0 = blockIdx.x * 128, n0 = blockIdx.y * 128;
    int wm = (warp & 3) * 32;
    int wn = (warp >> 2) * 64;

    // cp.async slot mapping (2 A-chunks + 2 B-chunks of 16B per thread per stage)
    int am0 = t >> 2,            akq0 = (t & 3) * 8;
    int am1 = (t + 256) >> 2,    akq1 = (t & 3) * 8;     // (t+256)&3 == t&3
    int bk0 = t >> 4,            bn0 = (t & 15) * 8;
    int bk1 = (t + 256) >> 4,    bn1 = (t & 15) * 8;

    #define GISSUE(st, k0) do { \
        unsigned ab = sbase + GSM_A(st); \
        unsigned bb = sbase + GSM_B(st); \
        cp16(ab + (am0 * 40 + akq0) * 2, A + (size_t)(m0 + am0) * Cc + (k0) + akq0); \
        cp16(ab + (am1 * 40 + akq1) * 2, A + (size_t)(m0 + am1) * Cc + (k0) + akq1); \
        cp16(bb + (bk0 * 136 + bn0) * 2, BT + (size_t)((k0) + bk0) * ldb + n0 + bn0); \
        cp16(bb + (bk1 * 136 + bn1) * 2, BT + (size_t)((k0) + bk1) * ldb + n0 + bn1); \
    } while (0)

    float acc[2][8][4];
    #pragma unroll
    for (int i = 0; i < 2; i++)
        #pragma unroll
        for (int j = 0; j < 8; j++)
            #pragma unroll
            for (int q = 0; q < 4; q++) acc[i][j][q] = 0.f;

    GISSUE(0, 0);  CP_COMMIT();
    GISSUE(1, 32); CP_COMMIT();

    #pragma unroll 1
    for (int iter = 0; iter < 8; iter++) {
        if (iter < 7) asm volatile("cp.async.wait_group 1;" ::: "memory");
        else          asm volatile("cp.async.wait_group 0;" ::: "memory");
        __syncthreads();
        if (iter < 6) {
            int st = iter + 2;
            int buf = st - (st >= 6 ? 6 : (st >= 3 ? 3 : 0));
            GISSUE(buf, st * 32);
            CP_COMMIT();
        }
        int s = iter - (iter >= 6 ? 6 : (iter >= 3 ? 3 : 0));  // iter % 3
        unsigned ab = sbase + GSM_A(s);
        unsigned bb = sbase + GSM_B(s);
        #pragma unroll
        for (int kk = 0; kk < 32; kk += 16) {
            unsigned a[2][4], b[8][2];
            #pragma unroll
            for (int i = 0; i < 2; i++) {
                unsigned addr = ab + ((wm + i * 16 + (lane & 15)) * 40 + kk + (lane >> 4) * 8) * 2;
                LDMX4(a[i][0], a[i][1], a[i][2], a[i][3], addr);
            }
            #pragma unroll
            for (int j = 0; j < 4; j++) {
                unsigned addr = bb + ((kk + (lane & 15)) * 136 + wn + j * 16 + (lane >> 4) * 8) * 2;
                unsigned r0, r1, r2, r3;
                LDMX4T(r0, r1, r2, r3, addr);
                b[2 * j][0] = r0; b[2 * j][1] = r1;
                b[2 * j + 1][0] = r2; b[2 * j + 1][1] = r3;
            }
            #pragma unroll
            for (int i = 0; i < 2; i++)
                #pragma unroll
                for (int j = 0; j < 8; j++)
                    MMABF16(acc[i][j][0], acc[i][j][1], acc[i][j][2], acc[i][j][3],
                            a[i][0], a[i][1], a[i][2], a[i][3], b[j][0], b[j][1]);
        }
    }
    #undef GISSUE

    #pragma unroll
    for (int i = 0; i < 2; i++) {
        int mrow = m0 + wm + i * 16 + (lane >> 2);
        #pragma unroll
        for (int j = 0; j < 8; j++) {
            int n = n0 + wn + j * 8 + (lane & 3) * 2;
            float b0, b1, b2, b3;
            if (BIASMODE == 0) {
                b0 = bias[n]; b1 = bias[n + 1]; b2 = b0; b3 = b1;
            } else {
                int h0 = mrow / 400, h1 = (mrow + 8) / 400;
                b0 = bias[(size_t)h0 * biasld + n]; b1 = bias[(size_t)h0 * biasld + n + 1];
                b2 = bias[(size_t)h1 * biasld + n]; b3 = bias[(size_t)h1 * biasld + n + 1];
            }
            float v00 = acc[i][j][0] + b0, v01 = acc[i][j][1] + b1;
            float v10 = acc[i][j][2] + b2, v11 = acc[i][j][3] + b3;
            if (OUTMODE == 1) {
                __nv_bfloat16* o = (n < 256) ? outA : outB;
                int col = n & 255;
                *(__nv_bfloat162*)(o + (size_t)mrow * Cc + col) = __floats2bfloat162_rn(v00, v01);
                *(__nv_bfloat162*)(o + (size_t)(mrow + 8) * Cc + col) = __floats2bfloat162_rn(v10, v11);
            } else {
                int p0 = (mrow & 127) * W2c + (mrow >> 7);
                int p1 = ((mrow + 8) & 127) * W2c + ((mrow + 8) >> 7);
                int s0 = d_sidx[sidx_off + p0];
                int s1 = d_sidx[sidx_off + p1];
                atomicAdd(&restP[(size_t)s0 * Cc + n],     v00);
                atomicAdd(&restP[(size_t)s0 * Cc + n + 1], v01);
                atomicAdd(&restP[(size_t)s1 * Cc + n],     v10);
                atomicAdd(&restP[(size_t)s1 * Cc + n + 1], v11);
            }
        }
    }
}

// ---------------- flash attention, fp32x2 packed math ----------------
__global__ __launch_bounds__(128) void k_attn() {
    int w = blockIdx.x, h = blockIdx.y, r = threadIdx.x;
    __shared__ float Ks[H2c * DHc];
    __shared__ float Vs[H2c * DHc];
    #pragma unroll
    for (int it = 0; it < 2; it++) {
        int g = it * 128 + r;
        int hh = g >> 2, dq = (g & 3) * 8;
        size_t src = ((size_t)(hh * W2c + w) * Cc + h * DHc + dq) >> 3;
        bf8_to_f(((const uint4*)d_kkbf)[src], Ks + g * 8);
        bf8_to_f(((const uint4*)d_vvbf)[src], Vs + g * 8);
    }
    __syncthreads();
    float q[DHc];
    const uint4* qp = (const uint4*)(d_qqbf + (size_t)(w * H1c + r) * Cc + h * DHc);
    #pragma unroll
    for (int d = 0; d < 4; d++) bf8_to_f(qp[d], q + d * 8);
    unsigned long long q2[16];
    #pragma unroll
    for (int i = 0; i < 16; i++) q2[i] = pk2(q[2 * i], q[2 * i + 1]);

    float m_run = -INFINITY, l_run = 0.f;
    unsigned long long vacc[16];
    #pragma unroll
    for (int i = 0; i < 16; i++) vacc[i] = 0ULL;

    #pragma unroll
    for (int kc = 0; kc < H2c; kc += 16) {
        float sc[16];
        float cmax = -INFINITY;
        #pragma unroll
        for (int k = 0; k < 16; k++) {
            const unsigned long long* K2 = (const unsigned long long*)(Ks + (kc + k) * DHc);
            unsigned long long a2 = 0ULL;
            #pragma unroll
            for (int i = 0; i < 16; i++) a2 = fma2(q2[i], K2[i], a2);
            float lo, hi; upk2(a2, lo, hi);
            float a = (lo + hi) * 0.17677669529663687f;  // 1/sqrt(32)
            sc[k] = a;
            cmax = fmaxf(cmax, a);
        }
        float nm = fmaxf(m_run, cmax);
        float f = __expf(m_run - nm);
        l_run *= f;
        unsigned long long f2 = pk2(f, f);
        #pragma unroll
        for (int i = 0; i < 16; i++) vacc[i] = mul2(vacc[i], f2);
        #pragma unroll
        for (int k = 0; k < 16; k++) {
            float p = __expf(sc[k] - nm);
            l_run += p;
            unsigned long long p2 = pk2(p, p);
            const unsigned long long* V2 = (const unsigned long long*)(Vs + (kc + k) * DHc);
            #pragma unroll
            for (int i = 0; i < 16; i++) vacc[i] = fma2(p2, V2[i], vacc[i]);
        }
        m_run = nm;
    }
    float inv = 1.f / l_run;
    __nv_bfloat16* op = d_obf + (size_t)(w * H1c + r) * Cc + h * DHc;
    #pragma unroll
    for (int i = 0; i < 16; i++) {
        float lo, hi; upk2(vacc[i], lo, hi);
        *(__nv_bfloat162*)(op + 2 * i) = __floats2bfloat162_rn(lo * inv, hi * inv);
    }
}

// ---------------- zero rest/cnt ----------------
__global__ void k_zero() {
    size_t i = (size_t)blockIdx.x * 256 + threadIdx.x;
    float4 z = make_float4(0.f, 0.f, 0.f, 0.f);
    ((float4*)d_rest)[i] = z;                 // grid 4096*256 = HWp*Cc/4 exactly
    if (i < HWp / 4) ((float4*)d_cnt)[i] = z;
}

// ---------------- count scatter hits ----------------
__global__ void k_cnt(int ji) {
    int p = blockIdx.x * 256 + threadIdx.x;
    atomicAdd(&d_cnt[d_sidx[ji * NPTS + p]], 1.0f);
}

// ---------------- update (pass 1): at += rest/cnt, rezero rest/cnt ----------------
__global__ void k_update() {
    int hw = blockIdx.x, c = threadIdx.x;
    float cnt = d_cnt[hw];
    cnt = (cnt == 0.f) ? 1.f : cnt;
    size_t idx = (size_t)hw * Cc + c;
    d_at[idx] += d_rest[idx] / cnt;
    d_rest[idx] = 0.f;
    if (c == 0) d_cnt[hw] = 0.f;
}

// ---------------- final: out[c][hw] = at[hw][c] + 2*rest[hw][c]/cnt[hw] ----------------
__global__ void k_writeout(float* __restrict__ out) {
    __shared__ float tile[32][33];
    int hw0 = blockIdx.x * 32;
    int c0  = blockIdx.y * 32;
    int tx = threadIdx.x;
    for (int i = threadIdx.y; i < 32; i += 8) {
        float cnt = d_cnt[hw0 + i];
        cnt = (cnt == 0.f) ? 1.f : cnt;
        size_t idx = (size_t)(hw0 + i) * Cc + c0 + tx;
        tile[i][tx] = d_at[idx] + 2.f * d_rest[idx] / cnt;
    }
    __syncthreads();
    for (int i = threadIdx.y; i < 32; i += 8)
        out[(size_t)(c0 + i) * HWp + hw0 + tx] = tile[tx][i];
}

// ---------------- host launcher (single stream) ----------------
extern "C" void kernel_launch(void* const* d_in, const int* in_sizes, int n_in,
                              void* d_out, int out_size) {
    const float* list_a = (const float*)d_in[0];
    const float* list_b = (const float*)d_in[1];
    const float* rots   = (const float*)d_in[3];
    const float* fxs    = (const float*)d_in[5];
    const float* cxs    = (const float*)d_in[6];
    const float* pos_a  = (const float*)d_in[7];
    const float* pos_b  = (const float*)d_in[8];
    const float* Wq     = (const float*)d_in[9];
    const float* bq     = (const float*)d_in[10];
    const float* Wk     = (const float*)d_in[11];
    const float* bk     = (const float*)d_in[12];
    const float* Wv     = (const float*)d_in[13];
    const float* bv     = (const float*)d_in[14];
    const float* in_w   = (const float*)d_in[15];
    const float* in_b   = (const float*)d_in[16];
    const float* out_w  = (const float*)d_in[17];
    const float* out_b  = (const float*)d_in[18];
    float* out = (float*)d_out;

    float *p_bc, *p_poskv, *p_rest;
    __nv_bfloat16 *p_aseqbf, *p_btbf, *p_qqbf, *p_kkbf, *p_vvbf, *p_obf,
                  *p_WqT, *p_WkvT, *p_outwT;
    cudaGetSymbolAddress((void**)&p_bc,     d_bc);
    cudaGetSymbolAddress((void**)&p_poskv,  d_poskv);
    cudaGetSymbolAddress((void**)&p_rest,   d_rest);
    cudaGetSymbolAddress((void**)&p_aseqbf, d_aseqbf);
    cudaGetSymbolAddress((void**)&p_btbf,   d_btbf);
    cudaGetSymbolAddress((void**)&p_qqbf,   d_qqbf);
    cudaGetSymbolAddress((void**)&p_kkbf,   d_kkbf);
    cudaGetSymbolAddress((void**)&p_vvbf,   d_vvbf);
    cudaGetSymbolAddress((void**)&p_obf,    d_obf);
    cudaGetSymbolAddress((void**)&p_WqT,    d_WqT);
    cudaGetSymbolAddress((void**)&p_WkvT,   d_WkvT);
    cudaGetSymbolAddress((void**)&p_outwT,  d_outwT);

    cudaFuncSetAttribute(k_mma_gemm<1, 0>, cudaFuncAttributeMaxDynamicSharedMemorySize, GSM_TOTAL);
    cudaFuncSetAttribute(k_mma_gemm<1, 1>, cudaFuncAttributeMaxDynamicSharedMemorySize, GSM_TOTAL);
    cudaFuncSetAttribute(k_mma_gemm<2, 0>, cudaFuncAttributeMaxDynamicSharedMemorySize, GSM_TOTAL);

    // launch order: process-launch 5 (= my index 3) is the fused kv GEMM
    k_combine_all<<<dim3(Cc, 4), Cc>>>(Wq, Wk, Wv, in_w, bq, bk, bv, in_b, out_w);   // 0
    k_pos_proj<<<dim3(H2c, 2), Cc>>>(pos_b);                                         // 1
    k_b2bt<<<dim3(MK / 32, Cc / 32), dim3(32, 8)>>>(list_b);                         // 2
    k_mma_gemm<1, 1><<<dim3(MK / 128, 4), 256, GSM_TOTAL>>>(                         // 3 <- profiled
        p_btbf, p_WkvT, p_poskv, p_kkbf, p_vvbf, nullptr, 512, 512, 0);
    k_coords_all<<<dim3((NPTS + 255) / 256, 2), 256>>>(rots, fxs, cxs);              // 4
    k_transpose_in<<<dim3(HWp / 32, Cc / 32), dim3(32, 8)>>>(list_a);                // 5
    k_zero<<<4096, 256>>>();                                                         // 6

    for (int ji = 0; ji < 2; ji++) {
        if (ji == 1) {
            k_b2bt<<<dim3(MK / 32, Cc / 32), dim3(32, 8)>>>(list_b + (size_t)3 * Cc * MK);
            k_mma_gemm<1, 1><<<dim3(MK / 128, 4), 256, GSM_TOTAL>>>(
                p_btbf, p_WkvT, p_poskv, p_kkbf, p_vvbf, nullptr, 512, 512, 0);
        }
        k_build_aseq<<<NPTS / 4, 256>>>(pos_a, ji);
        k_mma_gemm<1, 0><<<dim3(MQ / 128, 2), 256, GSM_TOTAL>>>(
            p_aseqbf, p_WqT, p_bc, p_qqbf, p_qqbf, nullptr, 256, 0, 0);
        k_attn<<<dim3(W2c, 8), 128>>>();
        k_mma_gemm<2, 0><<<dim3(MQ / 128, 2), 256, GSM_TOTAL>>>(
            p_obf, p_outwT, out_b, nullptr, nullptr, p_rest, 256, 0, ji * NPTS);
        k_cnt<<<NPTS / 256, 256>>>(ji);
        if (ji == 0) k_update<<<HWp, Cc>>>();
    }
    k_writeout<<<dim3(HWp / 32, Cc / 32), dim3(32, 8)>>>(out);
}

// round 8
// speedup vs baseline: 4.8367x; 1.4523x over previous
#include <cuda_runtime.h>
#include <cuda_bf16.h>
#include <math.h>

// ---------------- problem constants ----------------
#define Cc    256
#define HWp   16384      // 128*128
#define Ww    128
#define H1c   128
#define H2c   64
#define W2c   400
#define NPTS  (H1c*W2c)  // 51200
#define MQ    NPTS
#define MK    (H2c*W2c)  // 25600
#define DHc   32

// ---------------- scratch (device globals; no runtime alloc) ----------------
__device__ float  d_at[HWp*Cc];             // working image, HWC layout
__device__ __nv_bfloat16 d_aseqbf[MQ*Cc];
__device__ __nv_bfloat16 d_btbf[MK*Cc];     // list_b slice transposed to [M][K] bf16
__device__ __nv_bfloat16 d_qqbf[MQ*Cc];
__device__ __nv_bfloat16 d_kkbf[MK*Cc];
__device__ __nv_bfloat16 d_vvbf[MK*Cc];
__device__ __nv_bfloat16 d_obf[MQ*Cc];
__device__ float  d_rest[HWp*Cc];
__device__ float  d_rest2[HWp*Cc];
__device__ float  d_cnt[HWp];
__device__ float  d_cnt2[HWp];
__device__ int4   d_gidx[2*NPTS];
__device__ float2 d_wxy[2*NPTS];
__device__ int    d_sidx[2*NPTS];
__device__ float  d_bc[3*Cc];               // combined biases
__device__ __nv_bfloat16 d_WqT[Cc*Cc];      // combined Q weight bf16 K-major [k][n]
__device__ __nv_bfloat16 d_WkvT[Cc*2*Cc];   // stacked K|V weights bf16 K-major [k][512]
__device__ __nv_bfloat16 d_outwT[Cc*Cc];    // out_w bf16 K-major [k][n]
__device__ float  d_poskv[H2c*2*Cc];        // stacked pos bias [h][512] (K|V)

__device__ __forceinline__ unsigned sptr(const void* p) {
    return (unsigned)__cvta_generic_to_shared(p);
}
__device__ __forceinline__ unsigned bf2u(float a, float b) {
    __nv_bfloat162 t = __floats2bfloat162_rn(a, b);
    return *(unsigned*)&t;
}
// -------- cp.async --------
__device__ __forceinline__ void cp16(unsigned saddr, const void* g) {
    asm volatile("cp.async.ca.shared.global [%0], [%1], 16;" :: "r"(saddr), "l"(g));
}
#define CP_COMMIT() asm volatile("cp.async.commit_group;" ::: "memory")

#define LDMX4(r0,r1,r2,r3,addr) \
    asm volatile("ldmatrix.sync.aligned.m8n8.x4.shared.b16 {%0,%1,%2,%3},[%4];" \
        : "=r"(r0),"=r"(r1),"=r"(r2),"=r"(r3) : "r"(addr))
#define LDMX4T(r0,r1,r2,r3,addr) \
    asm volatile("ldmatrix.sync.aligned.m8n8.x4.trans.shared.b16 {%0,%1,%2,%3},[%4];" \
        : "=r"(r0),"=r"(r1),"=r"(r2),"=r"(r3) : "r"(addr))
#define MMABF16(c0,c1,c2,c3,a0,a1,a2,a3,b0,b1) \
    asm volatile("mma.sync.aligned.m16n8k16.row.col.f32.bf16.bf16.f32 " \
        "{%0,%1,%2,%3},{%4,%5,%6,%7},{%8,%9},{%0,%1,%2,%3};" \
        : "+f"(c0),"+f"(c1),"+f"(c2),"+f"(c3) \
        : "r"(a0),"r"(a1),"r"(a2),"r"(a3),"r"(b0),"r"(b1))

// ---------------- zero rest/rest2/cnt/cnt2 ----------------
__global__ void k_zero() {
    size_t i = (size_t)blockIdx.x * 256 + threadIdx.x;
    float4 z = make_float4(0.f, 0.f, 0.f, 0.f);
    ((float4*)d_rest)[i]  = z;      // grid covers HWp*Cc/4 exactly
    ((float4*)d_rest2)[i] = z;
    if (i < HWp / 4) { ((float4*)d_cnt)[i] = z; ((float4*)d_cnt2)[i] = z; }
}

// ---------------- coords for BOTH passes (+ scatter counts) ----------------
__global__ void k_coords_all(const float* __restrict__ rots, const float* __restrict__ fxs,
                             const float* __restrict__ cxs) {
    int p = blockIdx.x * blockDim.x + threadIdx.x;
    int ji = blockIdx.y;
    if (p >= NPTS) return;
    int j = ji * 3;  // cams 0 and 3
    int r = p / W2c, w = p % W2c;
    float fx = fxs[j], cx = cxs[j];
    float cth = rots[j * 9 + 0];
    float sth = rots[j * 9 + 3];
    float ang = atanf((w * 2.0f + 1.0f - cx) / fx);
    float cA = cosf(ang), sA = sinf(ang);
    float ca = sth * cA - cth * sA;
    float sa = cth * cA + sth * sA;
    float rmax = sqrtf(64.f * 64.f + 64.f * 64.f);
    float rad = ((float)r / 127.0f) * rmax;
    float x = 64.f + rad * ca;
    float y = 64.f - rad * sa;
    float xc = fminf(fmaxf(x, 0.f), 127.f);
    float yc = fminf(fmaxf(y, 0.f), 127.f);
    float x0 = floorf(xc), y0 = floorf(yc);
    float x1 = fminf(x0 + 1.f, 127.f), y1 = fminf(y0 + 1.f, 127.f);
    int x0i = (int)x0, x1i = (int)x1, y0i = (int)y0, y1i = (int)y1;
    int q = ji * NPTS + p;
    d_gidx[q] = make_int4(y0i * Ww + x0i, y0i * Ww + x1i, y1i * Ww + x0i, y1i * Ww + x1i);
    d_wxy[q]  = make_float2(xc - x0, yc - y0);
    int xi = (int)fminf(fmaxf(rintf(x), 0.f), 127.f);
    int yi = (int)fminf(fmaxf(rintf(y), 0.f), 127.f);
    int si = yi * Ww + xi;
    d_sidx[q] = si;
    atomicAdd((ji == 0 ? d_cnt : d_cnt2) + si, 1.0f);
}

// ---------------- combined weights + bias + bf16 K-major transposes ----------------
__global__ void k_combine_all(const float* __restrict__ Wq, const float* __restrict__ Wk,
                              const float* __restrict__ Wv, const float* __restrict__ in_w,
                              const float* __restrict__ bq, const float* __restrict__ bk,
                              const float* __restrict__ bv, const float* __restrict__ in_b,
                              const float* __restrict__ out_w) {
    int n = blockIdx.x, sel = blockIdx.y, c = threadIdx.x;
    if (sel == 3) {
        d_outwT[(size_t)c * Cc + n] = __float2bfloat16_rn(out_w[(size_t)n * Cc + c]);
        return;
    }
    const float* W = (sel == 0) ? Wq : ((sel == 1) ? Wk : Wv);
    const float* b = (sel == 0) ? bq : ((sel == 1) ? bk : bv);
    __shared__ float ir[Cc];
    __shared__ float red[8];
    ir[c] = in_w[(size_t)(sel * Cc + n) * Cc + c];
    __syncthreads();
    float s = 0.f;
    #pragma unroll 8
    for (int m = 0; m < Cc; m++) s += ir[m] * W[(size_t)m * Cc + c];
    if (sel == 0) d_WqT[(size_t)c * Cc + n] = __float2bfloat16_rn(s);
    else d_WkvT[(size_t)c * 512 + (sel - 1) * Cc + n] = __float2bfloat16_rn(s);
    float pb = ir[c] * b[c];
    #pragma unroll
    for (int o = 16; o > 0; o >>= 1) pb += __shfl_down_sync(0xffffffffu, pb, o);
    if ((c & 31) == 0) red[c >> 5] = pb;
    __syncthreads();
    if (c == 0) {
        float t = 0.f;
        #pragma unroll
        for (int i = 0; i < 8; i++) t += red[i];
        d_bc[sel * Cc + n] = t + in_b[sel * Cc + n];
    }
}

// poskv[h][which*256+n] = sum_c pos_b[h][c]*WkvT[c][which*256+n] + bc[(which+1)*256+n]
__global__ void k_pos_proj(const float* __restrict__ pos_b) {
    int h = blockIdx.x, which = blockIdx.y, n = threadIdx.x;
    __shared__ float pb[Cc];
    pb[n] = pos_b[(size_t)h * Cc + n];
    __syncthreads();
    float s = d_bc[(which + 1) * Cc + n];
    #pragma unroll 8
    for (int c = 0; c < Cc; c++)
        s += pb[c] * __bfloat162float(d_WkvT[(size_t)c * 512 + which * 256 + n]);
    d_poskv[(size_t)h * 512 + which * 256 + n] = s;
}

// ---------------- transpose+convert list_b slice [C][M] fp32 -> [M][C] bf16 ----------
__global__ void k_b2bt(const float* __restrict__ src) {
    __shared__ float tile[32][33];
    int m0 = blockIdx.x * 32, c0 = blockIdx.y * 32;
    int tx = threadIdx.x;
    for (int i = threadIdx.y; i < 32; i += 8)
        tile[i][tx] = src[(size_t)(c0 + i) * MK + m0 + tx];
    __syncthreads();
    for (int i = threadIdx.y; i < 32; i += 8)
        d_btbf[(size_t)(m0 + i) * Cc + c0 + tx] = __float2bfloat16_rn(tile[tx][i]);
}

// ---------------- input transpose: (C,H,W) -> (HW, C) ----------------
__global__ void k_transpose_in(const float* __restrict__ a) {
    __shared__ float tile[32][33];
    int hw0 = blockIdx.x * 32;
    int c0  = blockIdx.y * 32;
    for (int i = threadIdx.y; i < 32; i += 8)
        tile[i][threadIdx.x] = a[(size_t)(c0 + i) * HWp + hw0 + threadIdx.x];
    __syncthreads();
    for (int i = threadIdx.y; i < 32; i += 8)
        d_at[(size_t)(hw0 + i) * Cc + c0 + threadIdx.x] = tile[threadIdx.x][i];
}

// ---------------- a_seq = bilinear(a_t) + pos_a  ->  bf16 ----------------
__global__ __launch_bounds__(256) void k_build_aseq(const float* __restrict__ pos_a, int ji) {
    int tx = threadIdx.x & 63;
    int ty = threadIdx.x >> 6;
    int p  = blockIdx.x * 4 + ty;
    int r = p / W2c, w = p % W2c;
    int q = ji * NPTS + p;
    int4 g = d_gidx[q];
    float2 wt = d_wxy[q];
    float w11 = wt.x * wt.y;
    float w01 = wt.x - w11;
    float w10 = wt.y - w11;
    float w00 = 1.f - wt.x - wt.y + w11;
    float4 v00 = ((const float4*)(d_at + (size_t)g.x * Cc))[tx];
    float4 v01 = ((const float4*)(d_at + (size_t)g.y * Cc))[tx];
    float4 v10 = ((const float4*)(d_at + (size_t)g.z * Cc))[tx];
    float4 v11 = ((const float4*)(d_at + (size_t)g.w * Cc))[tx];
    float4 pa  = ((const float4*)(pos_a + (size_t)r * Cc))[tx];
    float o0 = v00.x * w00 + v01.x * w01 + v10.x * w10 + v11.x * w11 + pa.x;
    float o1 = v00.y * w00 + v01.y * w01 + v10.y * w10 + v11.y * w11 + pa.y;
    float o2 = v00.z * w00 + v01.z * w01 + v10.z * w10 + v11.z * w11 + pa.z;
    float o3 = v00.w * w00 + v01.w * w01 + v10.w * w10 + v11.w * w11 + pa.w;
    int row = w * H1c + r;
    uint2 u = {bf2u(o0, o1), bf2u(o2, o3)};
    *(uint2*)(d_aseqbf + (size_t)row * Cc + tx * 4) = u;
}

// ================= cp.async pipelined bf16 mma GEMM (unchanged engine) =================
#define GSM_A(st)  ((st) * 10240)
#define GSM_B(st)  (30720 + (st) * 8704)
#define GSM_TOTAL  56832
template<int OUTMODE, int BIASMODE>
__global__ __launch_bounds__(256) void k_mma_gemm(const __nv_bfloat16* __restrict__ A,
                                                  const __nv_bfloat16* __restrict__ BT,
                                                  const float* __restrict__ bias,
                                                  __nv_bfloat16* __restrict__ outA,
                                                  __nv_bfloat16* __restrict__ outB,
                                                  float* __restrict__ restP,
                                                  int ldb, int biasld, int sidx_off) {
    extern __shared__ __align__(16) char gsm[];
    unsigned sbase = sptr(gsm);
    int t = threadIdx.x, lane = t & 31, warp = t >> 5;
    int m0 = blockIdx.x * 128, n0 = blockIdx.y * 128;
    int wm = (warp & 3) * 32;
    int wn = (warp >> 2) * 64;

    int am0 = t >> 2,            akq0 = (t & 3) * 8;
    int am1 = (t + 256) >> 2,    akq1 = (t & 3) * 8;
    int bk0 = t >> 4,            bn0 = (t & 15) * 8;
    int bk1 = (t + 256) >> 4,    bn1 = (t & 15) * 8;

    #define GISSUE(st, k0) do { \
        unsigned ab = sbase + GSM_A(st); \
        unsigned bb = sbase + GSM_B(st); \
        cp16(ab + (am0 * 40 + akq0) * 2, A + (size_t)(m0 + am0) * Cc + (k0) + akq0); \
        cp16(ab + (am1 * 40 + akq1) * 2, A + (size_t)(m0 + am1) * Cc + (k0) + akq1); \
        cp16(bb + (bk0 * 136 + bn0) * 2, BT + (size_t)((k0) + bk0) * ldb + n0 + bn0); \
        cp16(bb + (bk1 * 136 + bn1) * 2, BT + (size_t)((k0) + bk1) * ldb + n0 + bn1); \
    } while (0)

    float acc[2][8][4];
    #pragma unroll
    for (int i = 0; i < 2; i++)
        #pragma unroll
        for (int j = 0; j < 8; j++)
            #pragma unroll
            for (int q = 0; q < 4; q++) acc[i][j][q] = 0.f;

    GISSUE(0, 0);  CP_COMMIT();
    GISSUE(1, 32); CP_COMMIT();

    #pragma unroll 1
    for (int iter = 0; iter < 8; iter++) {
        if (iter < 7) asm volatile("cp.async.wait_group 1;" ::: "memory");
        else          asm volatile("cp.async.wait_group 0;" ::: "memory");
        __syncthreads();
        if (iter < 6) {
            int st = iter + 2;
            int buf = st - (st >= 6 ? 6 : (st >= 3 ? 3 : 0));
            GISSUE(buf, st * 32);
            CP_COMMIT();
        }
        int s = iter - (iter >= 6 ? 6 : (iter >= 3 ? 3 : 0));
        unsigned ab = sbase + GSM_A(s);
        unsigned bb = sbase + GSM_B(s);
        #pragma unroll
        for (int kk = 0; kk < 32; kk += 16) {
            unsigned a[2][4], b[8][2];
            #pragma unroll
            for (int i = 0; i < 2; i++) {
                unsigned addr = ab + ((wm + i * 16 + (lane & 15)) * 40 + kk + (lane >> 4) * 8) * 2;
                LDMX4(a[i][0], a[i][1], a[i][2], a[i][3], addr);
            }
            #pragma unroll
            for (int j = 0; j < 4; j++) {
                unsigned addr = bb + ((kk + (lane & 15)) * 136 + wn + j * 16 + (lane >> 4) * 8) * 2;
                unsigned r0, r1, r2, r3;
                LDMX4T(r0, r1, r2, r3, addr);
                b[2 * j][0] = r0; b[2 * j][1] = r1;
                b[2 * j + 1][0] = r2; b[2 * j + 1][1] = r3;
            }
            #pragma unroll
            for (int i = 0; i < 2; i++)
                #pragma unroll
                for (int j = 0; j < 8; j++)
                    MMABF16(acc[i][j][0], acc[i][j][1], acc[i][j][2], acc[i][j][3],
                            a[i][0], a[i][1], a[i][2], a[i][3], b[j][0], b[j][1]);
        }
    }
    #undef GISSUE

    #pragma unroll
    for (int i = 0; i < 2; i++) {
        int mrow = m0 + wm + i * 16 + (lane >> 2);
        #pragma unroll
        for (int j = 0; j < 8; j++) {
            int n = n0 + wn + j * 8 + (lane & 3) * 2;
            float b0, b1, b2, b3;
            if (BIASMODE == 0) {
                b0 = bias[n]; b1 = bias[n + 1]; b2 = b0; b3 = b1;
            } else {
                int h0 = mrow / 400, h1 = (mrow + 8) / 400;
                b0 = bias[(size_t)h0 * biasld + n]; b1 = bias[(size_t)h0 * biasld + n + 1];
                b2 = bias[(size_t)h1 * biasld + n]; b3 = bias[(size_t)h1 * biasld + n + 1];
            }
            float v00 = acc[i][j][0] + b0, v01 = acc[i][j][1] + b1;
            float v10 = acc[i][j][2] + b2, v11 = acc[i][j][3] + b3;
            if (OUTMODE == 1) {
                __nv_bfloat16* o = (n < 256) ? outA : outB;
                int col = n & 255;
                *(__nv_bfloat162*)(o + (size_t)mrow * Cc + col) = __floats2bfloat162_rn(v00, v01);
                *(__nv_bfloat162*)(o + (size_t)(mrow + 8) * Cc + col) = __floats2bfloat162_rn(v10, v11);
            } else {
                int p0 = (mrow & 127) * W2c + (mrow >> 7);
                int p1 = ((mrow + 8) & 127) * W2c + ((mrow + 8) >> 7);
                int s0 = d_sidx[sidx_off + p0];
                int s1 = d_sidx[sidx_off + p1];
                atomicAdd(&restP[(size_t)s0 * Cc + n],     v00);
                atomicAdd(&restP[(size_t)s0 * Cc + n + 1], v01);
                atomicAdd(&restP[(size_t)s1 * Cc + n],     v10);
                atomicAdd(&restP[(size_t)s1 * Cc + n + 1], v11);
            }
        }
    }
}

// ---------------- tensor-core flash attention: grid (w=400, h=8), 128 threads ----------
// S = Q(128x32) @ K^T(32x64), softmax in fragments, O = P(128x64) @ V(64x32).
__global__ __launch_bounds__(128) void k_attn_tc() {
    int w = blockIdx.x, h = blockIdx.y;
    int t = threadIdx.x, lane = t & 31, warp = t >> 5;
    __shared__ __align__(16) __nv_bfloat16 Qs[128 * 40];
    __shared__ __align__(16) __nv_bfloat16 Ks[64 * 40];
    __shared__ __align__(16) __nv_bfloat16 Vs[64 * 40];

    // load Q (128x32 bf16 = 512 uint4)
    #pragma unroll
    for (int i = 0; i < 4; i++) {
        int slot = i * 128 + t;
        int row = slot >> 2, q4 = slot & 3;
        uint4 v = *(const uint4*)(d_qqbf + (size_t)(w * H1c + row) * Cc + h * DHc + q4 * 8);
        *(uint4*)(Qs + row * 40 + q4 * 8) = v;
    }
    // load K, V (64x32 each = 256 uint4 each)
    #pragma unroll
    for (int i = 0; i < 2; i++) {
        int slot = i * 128 + t;
        int key = slot >> 2, q4 = slot & 3;
        size_t src = (size_t)(key * W2c + w) * Cc + h * DHc + q4 * 8;
        *(uint4*)(Ks + key * 40 + q4 * 8) = *(const uint4*)(d_kkbf + src);
        *(uint4*)(Vs + key * 40 + q4 * 8) = *(const uint4*)(d_vvbf + src);
    }
    __syncthreads();

    int wm = warp * 32;
    // Q A-fragments: 2 m-tiles x 2 k16-steps
    unsigned qa[2][2][4];
    #pragma unroll
    for (int i = 0; i < 2; i++)
        #pragma unroll
        for (int ks = 0; ks < 2; ks++) {
            unsigned addr = sptr(Qs + (wm + i * 16 + (lane & 15)) * 40 + ks * 16 + (lane >> 4) * 8);
            LDMX4(qa[i][ks][0], qa[i][ks][1], qa[i][ks][2], qa[i][ks][3], addr);
        }

    // S accumulators: 2 m-tiles x 8 n8-tiles
    float sacc[2][8][4];
    #pragma unroll
    for (int i = 0; i < 2; i++)
        #pragma unroll
        for (int j = 0; j < 8; j++)
            #pragma unroll
            for (int q = 0; q < 4; q++) sacc[i][j][q] = 0.f;

    // B-fragments of K^T from Ks[n=key][k=d] via NON-trans ldmatrix
    #pragma unroll
    for (int ks = 0; ks < 2; ks++) {
        #pragma unroll
        for (int ng = 0; ng < 4; ng++) {   // n groups of 16 keys
            int row = ng * 16 + ((lane >> 4) & 1) * 8 + (lane & 7);
            int col = ((lane >> 3) & 1) * 8 + ks * 16;
            unsigned r0, r1, r2, r3;
            LDMX4(r0, r1, r2, r3, sptr(Ks + row * 40 + col));
            #pragma unroll
            for (int i = 0; i < 2; i++) {
                MMABF16(sacc[i][2 * ng][0], sacc[i][2 * ng][1], sacc[i][2 * ng][2], sacc[i][2 * ng][3],
                        qa[i][ks][0], qa[i][ks][1], qa[i][ks][2], qa[i][ks][3], r0, r1);
                MMABF16(sacc[i][2 * ng + 1][0], sacc[i][2 * ng + 1][1], sacc[i][2 * ng + 1][2], sacc[i][2 * ng + 1][3],
                        qa[i][ks][0], qa[i][ks][1], qa[i][ks][2], qa[i][ks][3], r2, r3);
            }
        }
    }

    // softmax in fragments (rows: slot0 = lane/4, slot1 = lane/4+8 per m-tile)
    const float sc = 0.17677669529663687f;  // 1/sqrt(32)
    float mx[2][2], ls[2][2];
    #pragma unroll
    for (int i = 0; i < 2; i++) {
        mx[i][0] = -INFINITY; mx[i][1] = -INFINITY;
        #pragma unroll
        for (int j = 0; j < 8; j++) {
            mx[i][0] = fmaxf(mx[i][0], fmaxf(sacc[i][j][0], sacc[i][j][1]));
            mx[i][1] = fmaxf(mx[i][1], fmaxf(sacc[i][j][2], sacc[i][j][3]));
        }
    }
    #pragma unroll
    for (int i = 0; i < 2; i++)
        #pragma unroll
        for (int s = 0; s < 2; s++) {
            float v = mx[i][s];
            v = fmaxf(v, __shfl_xor_sync(0xffffffffu, v, 1));
            v = fmaxf(v, __shfl_xor_sync(0xffffffffu, v, 2));
            mx[i][s] = v;
        }
    #pragma unroll
    for (int i = 0; i < 2; i++) {
        ls[i][0] = 0.f; ls[i][1] = 0.f;
        #pragma unroll
        for (int j = 0; j < 8; j++) {
            sacc[i][j][0] = __expf((sacc[i][j][0] - mx[i][0]) * sc);
            sacc[i][j][1] = __expf((sacc[i][j][1] - mx[i][0]) * sc);
            sacc[i][j][2] = __expf((sacc[i][j][2] - mx[i][1]) * sc);
            sacc[i][j][3] = __expf((sacc[i][j][3] - mx[i][1]) * sc);
            ls[i][0] += sacc[i][j][0] + sacc[i][j][1];
            ls[i][1] += sacc[i][j][2] + sacc[i][j][3];
        }
    }
    #pragma unroll
    for (int i = 0; i < 2; i++)
        #pragma unroll
        for (int s = 0; s < 2; s++) {
            float v = ls[i][s];
            v += __shfl_xor_sync(0xffffffffu, v, 1);
            v += __shfl_xor_sync(0xffffffffu, v, 2);
            ls[i][s] = v;
        }

    // P A-fragments directly from S accumulators (k = keys, 4 k16-steps)
    unsigned pa[2][4][4];
    #pragma unroll
    for (int i = 0; i < 2; i++)
        #pragma unroll
        for (int s = 0; s < 4; s++) {
            pa[i][s][0] = bf2u(sacc[i][2 * s][0],     sacc[i][2 * s][1]);
            pa[i][s][1] = bf2u(sacc[i][2 * s][2],     sacc[i][2 * s][3]);
            pa[i][s][2] = bf2u(sacc[i][2 * s + 1][0], sacc[i][2 * s + 1][1]);
            pa[i][s][3] = bf2u(sacc[i][2 * s + 1][2], sacc[i][2 * s + 1][3]);
        }

    // O = P @ V: V from Vs[k=key][n=d] via trans ldmatrix (same as GEMM B path)
    float oacc[2][4][4];
    #pragma unroll
    for (int i = 0; i < 2; i++)
        #pragma unroll
        for (int j = 0; j < 4; j++)
            #pragma unroll
            for (int q = 0; q < 4; q++) oacc[i][j][q] = 0.f;
    #pragma unroll
    for (int s = 0; s < 4; s++) {
        #pragma unroll
        for (int jn = 0; jn < 2; jn++) {
            unsigned r0, r1, r2, r3;
            LDMX4T(r0, r1, r2, r3,
                   sptr(Vs + (s * 16 + (lane & 15)) * 40 + jn * 16 + (lane >> 4) * 8));
            #pragma unroll
            for (int i = 0; i < 2; i++) {
                MMABF16(oacc[i][2 * jn][0], oacc[i][2 * jn][1], oacc[i][2 * jn][2], oacc[i][2 * jn][3],
                        pa[i][s][0], pa[i][s][1], pa[i][s][2], pa[i][s][3], r0, r1);
                MMABF16(oacc[i][2 * jn + 1][0], oacc[i][2 * jn + 1][1], oacc[i][2 * jn + 1][2], oacc[i][2 * jn + 1][3],
                        pa[i][s][0], pa[i][s][1], pa[i][s][2], pa[i][s][3], r2, r3);
            }
        }
    }

    // write O / l
    #pragma unroll
    for (int i = 0; i < 2; i++) {
        float inv0 = 1.f / ls[i][0], inv1 = 1.f / ls[i][1];
        int r0w = w * H1c + wm + i * 16 + (lane >> 2);
        #pragma unroll
        for (int j = 0; j < 4; j++) {
            int col = h * DHc + j * 8 + (lane & 3) * 2;
            *(__nv_bfloat162*)(d_obf + (size_t)r0w * Cc + col) =
                __floats2bfloat162_rn(oacc[i][j][0] * inv0, oacc[i][j][1] * inv0);
            *(__nv_bfloat162*)(d_obf + (size_t)(r0w + 8) * Cc + col) =
                __floats2bfloat162_rn(oacc[i][j][2] * inv1, oacc[i][j][3] * inv1);
        }
    }
}

// ---------------- update (pass 1): at += rest/cnt ----------------
__global__ void k_update() {
    int hw = blockIdx.x, c = threadIdx.x;
    float cnt = d_cnt[hw];
    cnt = (cnt == 0.f) ? 1.f : cnt;
    size_t idx = (size_t)hw * Cc + c;
    d_at[idx] += d_rest[idx] / cnt;
}

// ---------------- final: out[c][hw] = at[hw][c] + 2*rest2[hw][c]/cnt2[hw] ----------------
__global__ void k_writeout(float* __restrict__ out) {
    __shared__ float tile[32][33];
    int hw0 = blockIdx.x * 32;
    int c0  = blockIdx.y * 32;
    int tx = threadIdx.x;
    for (int i = threadIdx.y; i < 32; i += 8) {
        float cnt = d_cnt2[hw0 + i];
        cnt = (cnt == 0.f) ? 1.f : cnt;
        size_t idx = (size_t)(hw0 + i) * Cc + c0 + tx;
        tile[i][tx] = d_at[idx] + 2.f * d_rest2[idx] / cnt;
    }
    __syncthreads();
    for (int i = threadIdx.y; i < 32; i += 8)
        out[(size_t)(c0 + i) * HWp + hw0 + tx] = tile[tx][i];
}

// ---------------- host launcher (single stream) ----------------
extern "C" void kernel_launch(void* const* d_in, const int* in_sizes, int n_in,
                              void* d_out, int out_size) {
    const float* list_a = (const float*)d_in[0];
    const float* list_b = (const float*)d_in[1];
    const float* rots   = (const float*)d_in[3];
    const float* fxs    = (const float*)d_in[5];
    const float* cxs    = (const float*)d_in[6];
    const float* pos_a  = (const float*)d_in[7];
    const float* pos_b  = (const float*)d_in[8];
    const float* Wq     = (const float*)d_in[9];
    const float* bq     = (const float*)d_in[10];
    const float* Wk     = (const float*)d_in[11];
    const float* bk     = (const float*)d_in[12];
    const float* Wv     = (const float*)d_in[13];
    const float* bv     = (const float*)d_in[14];
    const float* in_w   = (const float*)d_in[15];
    const float* in_b   = (const float*)d_in[16];
    const float* out_w  = (const float*)d_in[17];
    const float* out_b  = (const float*)d_in[18];
    float* out = (float*)d_out;

    float *p_bc, *p_poskv, *p_rest, *p_rest2;
    __nv_bfloat16 *p_aseqbf, *p_btbf, *p_qqbf, *p_kkbf, *p_vvbf, *p_obf,
                  *p_WqT, *p_WkvT, *p_outwT;
    cudaGetSymbolAddress((void**)&p_bc,     d_bc);
    cudaGetSymbolAddress((void**)&p_poskv,  d_poskv);
    cudaGetSymbolAddress((void**)&p_rest,   d_rest);
    cudaGetSymbolAddress((void**)&p_rest2,  d_rest2);
    cudaGetSymbolAddress((void**)&p_aseqbf, d_aseqbf);
    cudaGetSymbolAddress((void**)&p_btbf,   d_btbf);
    cudaGetSymbolAddress((void**)&p_qqbf,   d_qqbf);
    cudaGetSymbolAddress((void**)&p_kkbf,   d_kkbf);
    cudaGetSymbolAddress((void**)&p_vvbf,   d_vvbf);
    cudaGetSymbolAddress((void**)&p_obf,    d_obf);
    cudaGetSymbolAddress((void**)&p_WqT,    d_WqT);
    cudaGetSymbolAddress((void**)&p_WkvT,   d_WkvT);
    cudaGetSymbolAddress((void**)&p_outwT,  d_outwT);

    cudaFuncSetAttribute(k_mma_gemm<1, 0>, cudaFuncAttributeMaxDynamicSharedMemorySize, GSM_TOTAL);
    cudaFuncSetAttribute(k_mma_gemm<1, 1>, cudaFuncAttributeMaxDynamicSharedMemorySize, GSM_TOTAL);
    cudaFuncSetAttribute(k_mma_gemm<2, 0>, cudaFuncAttributeMaxDynamicSharedMemorySize, GSM_TOTAL);

    k_zero<<<4096, 256>>>();                                                         // 0
    k_coords_all<<<dim3((NPTS + 255) / 256, 2), 256>>>(rots, fxs, cxs);              // 1
    k_combine_all<<<dim3(Cc, 4), Cc>>>(Wq, Wk, Wv, in_w, bq, bk, bv, in_b, out_w);   // 2
    k_pos_proj<<<dim3(H2c, 2), Cc>>>(pos_b);                                         // 3
    k_b2bt<<<dim3(MK / 32, Cc / 32), dim3(32, 8)>>>(list_b);                         // 4
    k_mma_gemm<1, 1><<<dim3(MK / 128, 4), 256, GSM_TOTAL>>>(                         // 5
        p_btbf, p_WkvT, p_poskv, p_kkbf, p_vvbf, nullptr, 512, 512, 0);
    k_transpose_in<<<dim3(HWp / 32, Cc / 32), dim3(32, 8)>>>(list_a);                // 6

    for (int ji = 0; ji < 2; ji++) {
        if (ji == 1) {
            k_b2bt<<<dim3(MK / 32, Cc / 32), dim3(32, 8)>>>(list_b + (size_t)3 * Cc * MK);
            k_mma_gemm<1, 1><<<dim3(MK / 128, 4), 256, GSM_TOTAL>>>(
                p_btbf, p_WkvT, p_poskv, p_kkbf, p_vvbf, nullptr, 512, 512, 0);
        }
        k_build_aseq<<<NPTS / 4, 256>>>(pos_a, ji);
        k_mma_gemm<1, 0><<<dim3(MQ / 128, 2), 256, GSM_TOTAL>>>(
            p_aseqbf, p_WqT, p_bc, p_qqbf, p_qqbf, nullptr, 256, 0, 0);
        k_attn_tc<<<dim3(W2c, 8), 128>>>();
        k_mma_gemm<2, 0><<<dim3(MQ / 128, 2), 256, GSM_TOTAL>>>(
            p_obf, p_outwT, out_b, nullptr, nullptr, ji == 0 ? p_rest : p_rest2,
            256, 0, ji * NPTS);
        if (ji == 0) k_update<<<HWp, Cc>>>();
    }
    k_writeout<<<dim3(HWp / 32, Cc / 32), dim3(32, 8)>>>(out);
}